// round 8
// baseline (speedup 1.0000x reference)
#include <cuda_runtime.h>
#include <cstdint>
#include <cstddef>

#define H 384
#define W 384
#define BATCH 2
#define NWIN 48

#define H1SZ ((size_t)BATCH*H*W*64)
#define H2SZ ((size_t)BATCH*H*W*32)

// ---------------- scratch ----------------
__device__ float g_h1[3*H1SZ];                  // conv1 out per branch, channel-last, tf32
__device__ float g_h2[3*H2SZ];                  // conv2 out per branch, channel-last, tf32
__device__ float g_feat[(size_t)BATCH*H*W*96];  // q|k|v channel-last
__device__ float g_aout[(size_t)BATCH*32*H*W];  // attention out (shifted space, NCHW)
__device__ float g_bf1[3*4608];
__device__ float g_bf2[3*18432];
__device__ float g_bf3[3*9216];

// ---------------- helpers ----------------
__device__ __forceinline__ float to_tf32(float f) {
    uint32_t u;
    asm("cvt.rna.tf32.f32 %0, %1;" : "=r"(u) : "f"(f));
    return __uint_as_float(u);
}
__device__ __forceinline__ void mma_tf32(float& c0, float& c1, float& c2, float& c3,
                                         uint32_t a0, uint32_t a1, uint32_t a2, uint32_t a3,
                                         uint32_t b0, uint32_t b1) {
    asm volatile("mma.sync.aligned.m16n8k8.row.col.f32.tf32.tf32.f32 "
                 "{%0,%1,%2,%3}, {%4,%5,%6,%7}, {%8,%9}, {%0,%1,%2,%3};"
                 : "+f"(c0), "+f"(c1), "+f"(c2), "+f"(c3)
                 : "r"(a0), "r"(a1), "r"(a2), "r"(a3), "r"(b0), "r"(b1));
}
__device__ __forceinline__ void ldmA(uint32_t& r0, uint32_t& r1, uint32_t& r2, uint32_t& r3,
                                     uint32_t addr) {
    asm volatile("ldmatrix.sync.aligned.m8n8.x4.shared.b16 {%0,%1,%2,%3}, [%4];"
                 : "=r"(r0), "=r"(r1), "=r"(r2), "=r"(r3) : "r"(addr));
}
__device__ __forceinline__ uint32_t smem_u32(const void* p) {
    return (uint32_t)__cvta_generic_to_shared(p);
}

// =====================================================================
// B-fragment prep -> paired-n fragment order for LDG.128 in mainloop:
// idx = ((ch*9 + dydx)*KSTEPS + kk)*NGRP*64 + (n>>1)*128 + lane*4 + (n&1)*2 + j
// ci = ch*CHK + kk*8 + (lane&3) + 4j ; co = n*8 + (lane>>2)
// =====================================================================
template<int CHK, int KSTEPS, int NCHUNK, int NGRP, int CINREAL>
__global__ void prep_b_k(const float* __restrict__ w0, const float* __restrict__ w1,
                         const float* __restrict__ w2, float* __restrict__ outBase)
{
    constexpr int SZ = NCHUNK*9*KSTEPS*NGRP*64;
    int idx = blockIdx.x*256 + threadIdx.x;
    if (idx >= SZ) return;
    const float* wt = blockIdx.y == 0 ? w0 : (blockIdx.y == 1 ? w1 : w2);
    float* outp = outBase + blockIdx.y*SZ;
    int j    = idx & 1;
    int nlow = (idx >> 1) & 1;
    int ln   = (idx >> 2) & 31;
    int np   = (idx >> 7) % (NGRP/2);
    int r2   = idx / (64*NGRP);
    int kk   = r2 % KSTEPS;
    int r3   = r2 / KSTEPS;
    int dydx = r3 % 9;
    int ch   = r3 / 9;
    int n  = np*2 + nlow;
    int ci = ch*CHK + kk*8 + (ln & 3) + 4*j;
    int co = n*8 + (ln >> 2);
    float v = 0.f;
    if (ci < CINREAL) v = to_tf32(wt[(co*CINREAL + ci)*9 + dydx]);
    outp[idx] = v;
}

// =====================================================================
// implicit-GEMM 3x3 conv, all 3 branches in one launch (z = br*2+bb).
// block 256 thr, tile 2 rows x 128 px. A slab smem, B from global frags.
// =====================================================================
template<int CHK, int PAD, int KSTEPS, int NCHUNK, int NGRP, int CINTOT,
         int OSTR, bool RELU, bool TF32OUT, bool NCHW3, bool FEAT>
__global__ __launch_bounds__(256, 2)
void gemm_conv_k(const float* __restrict__ in, const float* __restrict__ gB,
                 const float* __restrict__ bias0, const float* __restrict__ bias1,
                 const float* __restrict__ bias2, float* __restrict__ out,
                 size_t inStride, size_t outStride)
{
    extern __shared__ float sA[];   // [4][130][PAD]
    constexpr int BSZ = NCHUNK*9*KSTEPS*NGRP*64;

    const int z  = blockIdx.z;
    const int bb = z & 1;
    const int br = z >> 1;
    const float* bias = br == 0 ? bias0 : (br == 1 ? bias1 : bias2);
    in  += (size_t)br * inStride;
    out += (size_t)br * outStride;
    gB  += br * BSZ;
    const int outOff = FEAT ? br*32 : 0;

    const int x0 = blockIdx.x * 128;
    const int y0 = blockIdx.y * 2;
    const int tid = threadIdx.x;
    const int warp = tid >> 5, lane = tid & 31;
    const int warpRow = warp >> 2;          // 0..1
    const int pxBase  = (warp & 3) * 32;    // 0,32,64,96
    const int groupId = lane >> 2, quad = lane & 3;

    // ldmatrix per-lane offset: rows 0-15 (lane&15), k-half (lane>>4)*4
    const uint32_t aLane = smem_u32(sA) + (uint32_t)(((lane & 15)*PAD + (lane >> 4)*4) * 4);

    float acc[2][NGRP][4];
    #pragma unroll
    for (int n = 0; n < NGRP; n++) {
        float b0 = __ldg(&bias[n*8 + quad*2 + 0]);
        float b1 = __ldg(&bias[n*8 + quad*2 + 1]);
        #pragma unroll
        for (int m = 0; m < 2; m++) {
            acc[m][n][0] = b0; acc[m][n][1] = b1;
            acc[m][n][2] = b0; acc[m][n][3] = b1;
        }
    }

    #pragma unroll 1
    for (int ch = 0; ch < NCHUNK; ch++) {
        __syncthreads();
        if constexpr (NCHW3) {
            // conv1: 3 NCHW planes -> 8 k-slots (5 zero), all threads
            for (int i = tid; i < 4*130; i += 256) {
                int r = i / 130, px = i - r*130;
                int y = y0 - 1 + r;
                int x = x0 - 1 + px;
                float c0 = 0.f, c1 = 0.f, c2 = 0.f;
                if ((unsigned)y < (unsigned)H && (unsigned)x < (unsigned)W) {
                    c0 = in[((size_t)(bb*3 + 0)*H + y)*W + x];
                    c1 = in[((size_t)(bb*3 + 1)*H + y)*W + x];
                    c2 = in[((size_t)(bb*3 + 2)*H + y)*W + x];
                }
                float* dst = sA + (size_t)(r*130 + px)*PAD;
                *(float4*)dst     = make_float4(to_tf32(c0), to_tf32(c1), to_tf32(c2), 0.f);
                *(float4*)(dst+4) = make_float4(0.f, 0.f, 0.f, 0.f);
            }
        } else {
            constexpr int VPP = CHK/4;
            #pragma unroll
            for (int r = 0; r < 4; r++) {
                int y = y0 - 1 + r;
                bool yin = (unsigned)y < (unsigned)H;
                for (int i = tid; i < 130*VPP; i += 256) {
                    int px = i / VPP, v = i - px*VPP;
                    int x = x0 - 1 + px;
                    float4 val = make_float4(0.f, 0.f, 0.f, 0.f);
                    if (yin && (unsigned)x < (unsigned)W)
                        val = *(const float4*)(in + ((size_t)(bb*H + y)*W + x)*CINTOT + ch*CHK + v*4);
                    *(float4*)(sA + (size_t)(r*130 + px)*PAD + v*4) = val;
                }
            }
        }
        __syncthreads();

        #pragma unroll
        for (int dy = 0; dy < 3; dy++) {
            #pragma unroll
            for (int dx = 0; dx < 3; dx++) {
                const uint32_t aBase = aLane +
                    (uint32_t)((((warpRow + dy)*130 + pxBase + dx)*PAD) * 4);
                const float4* pb4 = (const float4*)
                    (gB + (size_t)((ch*9 + dy*3 + dx)*KSTEPS)*(NGRP*64)) + lane;
                #pragma unroll
                for (int kk = 0; kk < KSTEPS; kk++) {
                    uint32_t b0[NGRP], b1[NGRP];
                    #pragma unroll
                    for (int np = 0; np < NGRP/2; np++) {
                        float4 bv = __ldg(pb4 + (kk*NGRP*64 + np*128)/4);
                        b0[np*2+0] = __float_as_uint(bv.x);
                        b1[np*2+0] = __float_as_uint(bv.y);
                        b0[np*2+1] = __float_as_uint(bv.z);
                        b1[np*2+1] = __float_as_uint(bv.w);
                    }
                    #pragma unroll
                    for (int m = 0; m < 2; m++) {
                        uint32_t a0, a1, a2, a3;
                        ldmA(a0, a1, a2, a3, aBase + (uint32_t)((m*16*PAD + kk*8)*4));
                        #pragma unroll
                        for (int n = 0; n < NGRP; n++)
                            mma_tf32(acc[m][n][0], acc[m][n][1], acc[m][n][2], acc[m][n][3],
                                     a0, a1, a2, a3, b0[n], b1[n]);
                    }
                }
            }
        }
    }

    // ---- epilogue ----
    const int yOut = y0 + warpRow;
    #pragma unroll
    for (int m = 0; m < 2; m++) {
        #pragma unroll
        for (int hh = 0; hh < 2; hh++) {
            int px = pxBase + m*16 + groupId + hh*8;
            float* op = out + ((size_t)(bb*H + yOut)*W + x0 + px)*OSTR + outOff + quad*2;
            #pragma unroll
            for (int n = 0; n < NGRP; n++) {
                float v0 = acc[m][n][hh*2 + 0];
                float v1 = acc[m][n][hh*2 + 1];
                if (RELU) { v0 = fmaxf(v0, 0.f); v1 = fmaxf(v1, 0.f); }
                if (TF32OUT) { v0 = to_tf32(v0); v1 = to_tf32(v1); }
                *(float2*)(op + n*8) = make_float2(v0, v1);
            }
        }
    }
}

// =====================================================================
// shifted-window attention (reads feat channel-last 96)
// =====================================================================
__global__ __launch_bounds__(64)
void attn_k(const float* __restrict__ feat, const float* __restrict__ pos,
            float* __restrict__ aout)
{
    __shared__ float sK[64][32];
    __shared__ float sV[64][32];
    __shared__ float sPos[225];

    const int w  = blockIdx.x, bb = blockIdx.y;
    const int wh = w / NWIN, ww = w - wh*NWIN;
    const int tid = threadIdx.x;
    const int iy = tid >> 3, ix = tid & 7;
    const int sy = wh*8 + iy, sx = ww*8 + ix;
    int y = sy + 4; if (y >= H) y -= H;
    int x = sx + 4; if (x >= W) x -= W;

    for (int idx = tid; idx < 64*32; idx += 64) {
        int j = idx >> 5, c = idx & 31;
        int jy = j >> 3, jx = j & 7;
        int yy = wh*8 + jy + 4; if (yy >= H) yy -= H;
        int xx = ww*8 + jx + 4; if (xx >= W) xx -= W;
        const float* p = feat + ((size_t)(bb*H + yy)*W + xx)*96;
        sK[j][c] = p[32 + c];
        sV[j][c] = p[64 + c];
    }
    for (int idx = tid; idx < 225; idx += 64) sPos[idx] = pos[idx];

    float q[32];
    {
        const float* fp = feat + ((size_t)(bb*H + y)*W + x)*96;
        #pragma unroll
        for (int c = 0; c < 32; c += 4) {
            float4 v = *(const float4*)(fp + c);
            q[c] = v.x; q[c+1] = v.y; q[c+2] = v.z; q[c+3] = v.w;
        }
    }
    __syncthreads();

    const bool mR = (wh == NWIN-1);
    const bool mC = (ww == NWIN-1);
    const float scale = 0.35355339059327373f;
    const int posOff = (7 - iy)*15 + (7 - ix);

    #pragma unroll 1
    for (int h = 0; h < 4; h++) {
        float lg[64];
        float mx = -1e30f;
        #pragma unroll
        for (int j = 0; j < 64; j++) {
            const int jy = j >> 3, jx = j & 7;
            float d = 0.f;
            #pragma unroll
            for (int dd = 0; dd < 8; dd++)
                d = fmaf(q[h*8 + dd], sK[j][h*8 + dd], d);
            float l = d*scale + sPos[jy*15 + jx + posOff];
            bool msk = (mR && ((iy >= 4) != (jy >= 4))) ||
                       (mC && ((ix >= 4) != (jx >= 4)));
            l = msk ? -1e30f : l;
            lg[j] = l;
            mx = fmaxf(mx, l);
        }
        float s = 0.f;
        #pragma unroll
        for (int j = 0; j < 64; j++) {
            float e = __expf(lg[j] - mx);
            lg[j] = e;
            s += e;
        }
        const float inv = 1.f / s;
        float oh[8];
        #pragma unroll
        for (int dd = 0; dd < 8; dd++) oh[dd] = 0.f;
        #pragma unroll
        for (int j = 0; j < 64; j++) {
            float p = lg[j];
            #pragma unroll
            for (int dd = 0; dd < 8; dd++)
                oh[dd] = fmaf(p, sV[j][h*8 + dd], oh[dd]);
        }
        #pragma unroll
        for (int dd = 0; dd < 8; dd++)
            aout[((size_t)(bb*32 + h*8 + dd)*H + sy)*W + sx] = oh[dd]*inv;
    }
}

// =====================================================================
// output conv (32->3) + roll(+4,+4) + residual
// =====================================================================
#define TXO 16
#define TYO 8
#define NTO (TXO*TYO)
__global__ __launch_bounds__(NTO)
void conv_out_k(const float* __restrict__ in, const float* __restrict__ wt,
                const float* __restrict__ bias, const float* __restrict__ xin,
                float* __restrict__ out)
{
    constexpr int CIN = 32, COUT = 3, CHUNK = 16;
    __shared__ float sInb[CHUNK][TYO+2][TXO+2];
    __shared__ float sWb[COUT][CHUNK][9];

    const int bx = blockIdx.x * TXO, by = blockIdx.y * TYO, bb = blockIdx.z;
    const int tid = threadIdx.x;
    const int lx = tid % TXO, ly = tid / TXO;

    float acc[COUT];
    #pragma unroll
    for (int co = 0; co < COUT; co++) acc[co] = __ldg(&bias[co]);

    for (int c0 = 0; c0 < CIN; c0 += CHUNK) {
        __syncthreads();
        for (int idx = tid; idx < COUT*CHUNK*9; idx += NTO) {
            int co = idx / (CHUNK*9);
            int r  = idx - co*(CHUNK*9);
            int ci = r / 9;
            int t  = r - ci*9;
            sWb[co][ci][t] = wt[(co*CIN + c0 + ci)*9 + t];
        }
        {
            const int ty = tid >> 5, tx = tid & 31;
            for (int ci = 0; ci < CHUNK; ci++)
                for (int yy = ty; yy < TYO+2; yy += 4)
                    for (int xx = tx; xx < TXO+2; xx += 32) {
                        int gy = by + yy - 1, gx = bx + xx - 1;
                        float v = 0.f;
                        if ((unsigned)gy < (unsigned)H && (unsigned)gx < (unsigned)W)
                            v = in[((size_t)(bb*CIN + c0 + ci)*H + gy)*W + gx];
                        sInb[ci][yy][xx] = v;
                    }
        }
        __syncthreads();

        #pragma unroll 2
        for (int ci = 0; ci < CHUNK; ci++) {
            float r00 = sInb[ci][ly+0][lx+0], r01 = sInb[ci][ly+0][lx+1], r02 = sInb[ci][ly+0][lx+2];
            float r10 = sInb[ci][ly+1][lx+0], r11 = sInb[ci][ly+1][lx+1], r12 = sInb[ci][ly+1][lx+2];
            float r20 = sInb[ci][ly+2][lx+0], r21 = sInb[ci][ly+2][lx+1], r22 = sInb[ci][ly+2][lx+2];
            #pragma unroll
            for (int co = 0; co < COUT; co++) {
                const float* wp = &sWb[co][ci][0];
                float a = acc[co];
                a = fmaf(r00, wp[0], a);
                a = fmaf(r01, wp[1], a);
                a = fmaf(r02, wp[2], a);
                a = fmaf(r10, wp[3], a);
                a = fmaf(r11, wp[4], a);
                a = fmaf(r12, wp[5], a);
                a = fmaf(r20, wp[6], a);
                a = fmaf(r21, wp[7], a);
                a = fmaf(r22, wp[8], a);
                acc[co] = a;
            }
        }
    }

    const int gy = by + ly, gx = bx + lx;
    int oy = gy + 4; if (oy >= H) oy -= H;
    int ox = gx + 4; if (ox >= W) ox -= W;
    #pragma unroll
    for (int co = 0; co < COUT; co++) {
        size_t idx = ((size_t)(bb*COUT + co)*H + oy)*W + ox;
        out[idx] = xin[idx] + acc[co];
    }
}

// ---------------- launcher ----------------
extern "C" void kernel_launch(void* const* d_in, const int* in_sizes, int n_in,
                              void* d_out, int out_size)
{
    (void)in_sizes; (void)n_in; (void)out_size;
    const float* x   = (const float*)d_in[0];
    const float* wo  = (const float*)d_in[19];
    const float* bo  = (const float*)d_in[20];
    const float* pos = (const float*)d_in[21];
    float* out = (float*)d_out;

    float *h1, *h2, *feat, *aout, *bf1, *bf2, *bf3;
    cudaGetSymbolAddress((void**)&h1,   g_h1);
    cudaGetSymbolAddress((void**)&h2,   g_h2);
    cudaGetSymbolAddress((void**)&feat, g_feat);
    cudaGetSymbolAddress((void**)&aout, g_aout);
    cudaGetSymbolAddress((void**)&bf1,  g_bf1);
    cudaGetSymbolAddress((void**)&bf2,  g_bf2);
    cudaGetSymbolAddress((void**)&bf3,  g_bf3);

    constexpr int SM1  = 4*130*12*4;
    constexpr int SM23 = 4*130*36*4;
    cudaFuncSetAttribute((const void*)gemm_conv_k<32,36,4,2,4,64,32,true,true,false,false>,
                         cudaFuncAttributeMaxDynamicSharedMemorySize, SM23);
    cudaFuncSetAttribute((const void*)gemm_conv_k<32,36,4,1,4,32,96,false,false,false,true>,
                         cudaFuncAttributeMaxDynamicSharedMemorySize, SM23);

    // B-fragment prep (3 branches each, paired-n layout)
    prep_b_k<8, 1, 1, 8, 3 ><<<dim3(18, 3), 256>>>(
        (const float*)d_in[1], (const float*)d_in[7],  (const float*)d_in[13], bf1);
    prep_b_k<32,4, 2, 4, 64><<<dim3(72, 3), 256>>>(
        (const float*)d_in[3], (const float*)d_in[9],  (const float*)d_in[15], bf2);
    prep_b_k<32,4, 1, 4, 32><<<dim3(36, 3), 256>>>(
        (const float*)d_in[5], (const float*)d_in[11], (const float*)d_in[17], bf3);

    dim3 gg(W/128, H/2, BATCH*3);   // z = br*2 + bb
    gemm_conv_k<8, 12,1,1,8,3, 64,true, true, true, false><<<gg, 256, SM1 >>>(
        x, bf1,
        (const float*)d_in[2], (const float*)d_in[8], (const float*)d_in[14],
        h1, 0, H1SZ);
    gemm_conv_k<32,36,4,2,4,64,32,true, true, false,false><<<gg, 256, SM23>>>(
        h1, bf2,
        (const float*)d_in[4], (const float*)d_in[10], (const float*)d_in[16],
        h2, H1SZ, H2SZ);
    gemm_conv_k<32,36,4,1,4,32,96,false,false,false,true ><<<gg, 256, SM23>>>(
        h2, bf3,
        (const float*)d_in[6], (const float*)d_in[12], (const float*)d_in[18],
        feat, H2SZ, 0);

    attn_k<<<dim3(NWIN*NWIN, BATCH), 64>>>(feat, pos, aout);
    conv_out_k<<<dim3(W/TXO, H/TYO, BATCH), NTO>>>(aout, wo, bo, x, out);
}

// round 9
// speedup vs baseline: 1.4834x; 1.4834x over previous
#include <cuda_runtime.h>
#include <cuda_bf16.h>
#include <cstdint>
#include <cstddef>

#define H 384
#define W 384
#define BATCH 2
#define NWIN 48

#define H1SZ ((size_t)BATCH*H*W*64)   // elements per branch (bf16)
#define H2SZ ((size_t)BATCH*H*W*32)

// ---------------- scratch ----------------
__device__ __nv_bfloat16 g_h1[3*H1SZ];
__device__ __nv_bfloat16 g_h2[3*H2SZ];
__device__ __nv_bfloat16 g_feat[(size_t)BATCH*H*W*96];
__device__ float g_aout[(size_t)BATCH*32*H*W];
__device__ float    g_bf1[3*4608];     // conv1 B frags (tf32 floats)
__device__ uint32_t g_bf2[3*9216];     // conv2 B frags (bf16x2 packed)
__device__ uint32_t g_bf3[3*4608];     // conv3 B frags

// ---------------- helpers ----------------
__device__ __forceinline__ float to_tf32(float f) {
    uint32_t u;
    asm("cvt.rna.tf32.f32 %0, %1;" : "=r"(u) : "f"(f));
    return __uint_as_float(u);
}
__device__ __forceinline__ void mma_tf32(float& c0, float& c1, float& c2, float& c3,
                                         uint32_t a0, uint32_t a1, uint32_t a2, uint32_t a3,
                                         uint32_t b0, uint32_t b1) {
    asm volatile("mma.sync.aligned.m16n8k8.row.col.f32.tf32.tf32.f32 "
                 "{%0,%1,%2,%3}, {%4,%5,%6,%7}, {%8,%9}, {%0,%1,%2,%3};"
                 : "+f"(c0), "+f"(c1), "+f"(c2), "+f"(c3)
                 : "r"(a0), "r"(a1), "r"(a2), "r"(a3), "r"(b0), "r"(b1));
}
__device__ __forceinline__ void mma_bf16(float& c0, float& c1, float& c2, float& c3,
                                         uint32_t a0, uint32_t a1, uint32_t a2, uint32_t a3,
                                         uint32_t b0, uint32_t b1) {
    asm volatile("mma.sync.aligned.m16n8k16.row.col.f32.bf16.bf16.f32 "
                 "{%0,%1,%2,%3}, {%4,%5,%6,%7}, {%8,%9}, {%0,%1,%2,%3};"
                 : "+f"(c0), "+f"(c1), "+f"(c2), "+f"(c3)
                 : "r"(a0), "r"(a1), "r"(a2), "r"(a3), "r"(b0), "r"(b1));
}
__device__ __forceinline__ void ldmA(uint32_t& r0, uint32_t& r1, uint32_t& r2, uint32_t& r3,
                                     uint32_t addr) {
    asm volatile("ldmatrix.sync.aligned.m8n8.x4.shared.b16 {%0,%1,%2,%3}, [%4];"
                 : "=r"(r0), "=r"(r1), "=r"(r2), "=r"(r3) : "r"(addr));
}
__device__ __forceinline__ uint32_t smem_u32(const void* p) {
    return (uint32_t)__cvta_generic_to_shared(p);
}

// =====================================================================
// conv1 B prep (tf32 floats, paired-n layout for LDG.128) — as R8
// idx = dydx*NGRP*64 + (n>>1)*128 + lane*4 + (n&1)*2 + j
// =====================================================================
__global__ void prep_b1_k(const float* __restrict__ w0, const float* __restrict__ w1,
                          const float* __restrict__ w2, float* __restrict__ outBase)
{
    constexpr int SZ = 9*8*64;
    int idx = blockIdx.x*256 + threadIdx.x;
    if (idx >= SZ) return;
    const float* wt = blockIdx.y == 0 ? w0 : (blockIdx.y == 1 ? w1 : w2);
    float* outp = outBase + blockIdx.y*SZ;
    int j    = idx & 1;
    int nlow = (idx >> 1) & 1;
    int ln   = (idx >> 2) & 31;
    int np   = (idx >> 7) & 3;
    int dydx = idx >> 9;
    int n  = np*2 + nlow;
    int ci = (ln & 3) + 4*j;
    int co = n*8 + (ln >> 2);
    float v = 0.f;
    if (ci < 3) v = to_tf32(wt[(co*3 + ci)*9 + dydx]);
    outp[idx] = v;
}

// =====================================================================
// bf16 B prep: per (ch,dydx,kk): 256 uint32 = 32 lanes x {b0n0,b1n0,b0n1,b1n1}
// then +128: n2,n3.  b0 = pack(B[k0][co],B[k0+1][co]), k0=(lane&3)*2 (+8 for b1)
// =====================================================================
template<int KSTEPS, int NCHUNK, int CINREAL>
__global__ void prep_b2_k(const float* __restrict__ w0, const float* __restrict__ w1,
                          const float* __restrict__ w2, uint32_t* __restrict__ outBase)
{
    constexpr int SZ = NCHUNK*9*KSTEPS*256;
    int idx = blockIdx.x*256 + threadIdx.x;
    if (idx >= SZ) return;
    const float* wt = blockIdx.y == 0 ? w0 : (blockIdx.y == 1 ? w1 : w2);
    uint32_t* outp = outBase + blockIdx.y*SZ;
    int r    = idx & 3;
    int lane = (idx >> 2) & 31;
    int half = (idx >> 7) & 1;
    int rest = idx >> 8;
    int kk   = rest % KSTEPS;
    int rest2 = rest / KSTEPS;
    int dydx = rest2 % 9;
    int ch   = rest2 / 9;
    int n    = half*2 + (r >> 1);
    int breg = r & 1;
    int ci = ch*32 + kk*16 + (lane & 3)*2 + breg*8;
    int co = n*8 + (lane >> 2);
    __nv_bfloat162 pk = __floats2bfloat162_rn(
        wt[(co*CINREAL + ci + 0)*9 + dydx],
        wt[(co*CINREAL + ci + 1)*9 + dydx]);
    outp[idx] = *(uint32_t*)&pk;
}

// =====================================================================
// conv1: 3->64 implicit GEMM (tf32, K=8 with 3 real), out bf16 channel-last
// z = br*2 + bb. tile 2 rows x 128 px. PAD=12 floats (48B px stride).
// =====================================================================
__global__ __launch_bounds__(256, 2)
void conv1_gemm_k(const float* __restrict__ in, const float* __restrict__ gB,
                  const float* __restrict__ bias0, const float* __restrict__ bias1,
                  const float* __restrict__ bias2, __nv_bfloat16* __restrict__ out)
{
    extern __shared__ __align__(16) float sA[];   // [4][130][12]
    const int z  = blockIdx.z;
    const int bb = z & 1;
    const int br = z >> 1;
    const float* bias = br == 0 ? bias0 : (br == 1 ? bias1 : bias2);
    gB  += br * 4608;
    out += (size_t)br * H1SZ;

    const int x0 = blockIdx.x * 128;
    const int y0 = blockIdx.y * 2;
    const int tid = threadIdx.x;
    const int warp = tid >> 5, lane = tid & 31;
    const int warpRow = warp >> 2;
    const int pxBase  = (warp & 3) * 32;
    const int groupId = lane >> 2, quad = lane & 3;

    const uint32_t aLane = smem_u32(sA) + (uint32_t)(((lane & 15)*12 + (lane >> 4)*4) * 4);

    float acc[2][8][4];
    #pragma unroll
    for (int n = 0; n < 8; n++) {
        float b0 = __ldg(&bias[n*8 + quad*2 + 0]);
        float b1 = __ldg(&bias[n*8 + quad*2 + 1]);
        #pragma unroll
        for (int m = 0; m < 2; m++) {
            acc[m][n][0] = b0; acc[m][n][1] = b1;
            acc[m][n][2] = b0; acc[m][n][3] = b1;
        }
    }

    for (int i = tid; i < 4*130; i += 256) {
        int r = i / 130, px = i - r*130;
        int y = y0 - 1 + r;
        int x = x0 - 1 + px;
        float c0 = 0.f, c1 = 0.f, c2 = 0.f;
        if ((unsigned)y < (unsigned)H && (unsigned)x < (unsigned)W) {
            c0 = in[((size_t)(bb*3 + 0)*H + y)*W + x];
            c1 = in[((size_t)(bb*3 + 1)*H + y)*W + x];
            c2 = in[((size_t)(bb*3 + 2)*H + y)*W + x];
        }
        float* dst = sA + (size_t)(r*130 + px)*12;
        *(float4*)dst     = make_float4(to_tf32(c0), to_tf32(c1), to_tf32(c2), 0.f);
        *(float4*)(dst+4) = make_float4(0.f, 0.f, 0.f, 0.f);
    }
    __syncthreads();

    #pragma unroll
    for (int dy = 0; dy < 3; dy++) {
        #pragma unroll
        for (int dx = 0; dx < 3; dx++) {
            const uint32_t aBase = aLane + (uint32_t)((((warpRow + dy)*130 + pxBase + dx)*12) * 4);
            const float4* pb4 = (const float4*)(gB + (size_t)(dy*3 + dx)*512) + lane;
            uint32_t b0[8], b1[8];
            #pragma unroll
            for (int np = 0; np < 4; np++) {
                float4 bv = __ldg(pb4 + np*32);
                b0[np*2+0] = __float_as_uint(bv.x);
                b1[np*2+0] = __float_as_uint(bv.y);
                b0[np*2+1] = __float_as_uint(bv.z);
                b1[np*2+1] = __float_as_uint(bv.w);
            }
            #pragma unroll
            for (int m = 0; m < 2; m++) {
                uint32_t a0, a1, a2, a3;
                ldmA(a0, a1, a2, a3, aBase + (uint32_t)(m*16*12*4));
                #pragma unroll
                for (int n = 0; n < 8; n++)
                    mma_tf32(acc[m][n][0], acc[m][n][1], acc[m][n][2], acc[m][n][3],
                             a0, a1, a2, a3, b0[n], b1[n]);
            }
        }
    }

    const int yOut = y0 + warpRow;
    #pragma unroll
    for (int m = 0; m < 2; m++) {
        #pragma unroll
        for (int hh = 0; hh < 2; hh++) {
            int px = pxBase + m*16 + groupId + hh*8;
            __nv_bfloat16* op = out + ((size_t)(bb*H + yOut)*W + x0 + px)*64 + quad*2;
            #pragma unroll
            for (int n = 0; n < 8; n++) {
                float v0 = fmaxf(acc[m][n][hh*2 + 0], 0.f);
                float v1 = fmaxf(acc[m][n][hh*2 + 1], 0.f);
                *(__nv_bfloat162*)(op + n*8) = __floats2bfloat162_rn(v0, v1);
            }
        }
    }
}

// =====================================================================
// bf16 implicit-GEMM conv (conv2/conv3). tile 2 rows x 128 px, NGRP=4.
// A slab bf16: [4 rows][130 px][PADB=40] (80B px stride, ldmatrix conflict-free)
// =====================================================================
#define PADB 40
#define SMB (4*130*PADB*2)

template<int KSTEPS, int NCHUNK, int CINTOT, int OSTR, bool RELU, bool FEAT>
__global__ __launch_bounds__(256, 2)
void gemm_bf16_k(const __nv_bfloat16* __restrict__ in, const uint32_t* __restrict__ gB,
                 const float* __restrict__ bias0, const float* __restrict__ bias1,
                 const float* __restrict__ bias2, __nv_bfloat16* __restrict__ out,
                 size_t inStride, size_t outStride)
{
    extern __shared__ __align__(16) char sAb[];
    constexpr int BSZ = NCHUNK*9*KSTEPS*256;

    const int z  = blockIdx.z;
    const int bb = z & 1;
    const int br = z >> 1;
    const float* bias = br == 0 ? bias0 : (br == 1 ? bias1 : bias2);
    in  += (size_t)br * inStride;
    out += (size_t)br * outStride;
    gB  += br * BSZ;
    const int outOff = FEAT ? br*32 : 0;

    const int x0 = blockIdx.x * 128;
    const int y0 = blockIdx.y * 2;
    const int tid = threadIdx.x;
    const int warp = tid >> 5, lane = tid & 31;
    const int warpRow = warp >> 2;
    const int pxBase  = (warp & 3) * 32;
    const int groupId = lane >> 2, quad = lane & 3;

    // bf16 ldmatrix lane addr: row=(lane&15) stride 80B, k-half (lane>>4)*16B
    const uint32_t aLane = smem_u32(sAb) + (uint32_t)((lane & 15)*(PADB*2) + (lane >> 4)*16);

    float acc[2][4][4];
    #pragma unroll
    for (int n = 0; n < 4; n++) {
        float b0 = __ldg(&bias[n*8 + quad*2 + 0]);
        float b1 = __ldg(&bias[n*8 + quad*2 + 1]);
        #pragma unroll
        for (int m = 0; m < 2; m++) {
            acc[m][n][0] = b0; acc[m][n][1] = b1;
            acc[m][n][2] = b0; acc[m][n][3] = b1;
        }
    }

    #pragma unroll 1
    for (int ch = 0; ch < NCHUNK; ch++) {
        __syncthreads();
        #pragma unroll
        for (int r = 0; r < 4; r++) {
            int y = y0 - 1 + r;
            bool yin = (unsigned)y < (unsigned)H;
            for (int i = tid; i < 130*4; i += 256) {
                int px = i >> 2, v = i & 3;
                int x = x0 - 1 + px;
                uint4 val = make_uint4(0u, 0u, 0u, 0u);
                if (yin && (unsigned)x < (unsigned)W)
                    val = *(const uint4*)(in + ((size_t)(bb*H + y)*W + x)*CINTOT + ch*32 + v*8);
                *(uint4*)(sAb + (size_t)(r*130 + px)*(PADB*2) + v*16) = val;
            }
        }
        __syncthreads();

        #pragma unroll
        for (int dy = 0; dy < 3; dy++) {
            #pragma unroll
            for (int dx = 0; dx < 3; dx++) {
                const uint32_t aBase = aLane +
                    (uint32_t)(((warpRow + dy)*130 + pxBase + dx)*(PADB*2));
                const uint4* pb4 = (const uint4*)gB + ((ch*9 + dy*3 + dx)*KSTEPS)*64 + lane;
                #pragma unroll
                for (int kk = 0; kk < KSTEPS; kk++) {
                    uint4 L0 = __ldg(pb4 + kk*64);
                    uint4 L1 = __ldg(pb4 + kk*64 + 32);
                    #pragma unroll
                    for (int m = 0; m < 2; m++) {
                        uint32_t a0, a1, a2, a3;
                        ldmA(a0, a1, a2, a3, aBase + (uint32_t)(m*16*(PADB*2) + kk*32));
                        mma_bf16(acc[m][0][0], acc[m][0][1], acc[m][0][2], acc[m][0][3],
                                 a0, a1, a2, a3, L0.x, L0.y);
                        mma_bf16(acc[m][1][0], acc[m][1][1], acc[m][1][2], acc[m][1][3],
                                 a0, a1, a2, a3, L0.z, L0.w);
                        mma_bf16(acc[m][2][0], acc[m][2][1], acc[m][2][2], acc[m][2][3],
                                 a0, a1, a2, a3, L1.x, L1.y);
                        mma_bf16(acc[m][3][0], acc[m][3][1], acc[m][3][2], acc[m][3][3],
                                 a0, a1, a2, a3, L1.z, L1.w);
                    }
                }
            }
        }
    }

    const int yOut = y0 + warpRow;
    #pragma unroll
    for (int m = 0; m < 2; m++) {
        #pragma unroll
        for (int hh = 0; hh < 2; hh++) {
            int px = pxBase + m*16 + groupId + hh*8;
            __nv_bfloat16* op = out + ((size_t)(bb*H + yOut)*W + x0 + px)*OSTR + outOff + quad*2;
            #pragma unroll
            for (int n = 0; n < 4; n++) {
                float v0 = acc[m][n][hh*2 + 0];
                float v1 = acc[m][n][hh*2 + 1];
                if (RELU) { v0 = fmaxf(v0, 0.f); v1 = fmaxf(v1, 0.f); }
                *(__nv_bfloat162*)(op + n*8) = __floats2bfloat162_rn(v0, v1);
            }
        }
    }
}

// =====================================================================
// shifted-window attention (reads feat bf16 channel-last 96, fp32 math)
// =====================================================================
__global__ __launch_bounds__(64)
void attn_k(const __nv_bfloat16* __restrict__ feat, const float* __restrict__ pos,
            float* __restrict__ aout)
{
    __shared__ float sK[64][32];
    __shared__ float sV[64][32];
    __shared__ float sPos[225];

    const int w  = blockIdx.x, bb = blockIdx.y;
    const int wh = w / NWIN, ww = w - wh*NWIN;
    const int tid = threadIdx.x;
    const int iy = tid >> 3, ix = tid & 7;
    const int sy = wh*8 + iy, sx = ww*8 + ix;
    int y = sy + 4; if (y >= H) y -= H;
    int x = sx + 4; if (x >= W) x -= W;

    // vectorized bf16 loads: 8 bf16 per uint4
    for (int idx = tid; idx < 64*4; idx += 64) {
        int j = idx >> 2, part = idx & 3;
        int jy = j >> 3, jx = j & 7;
        int yy = wh*8 + jy + 4; if (yy >= H) yy -= H;
        int xx = ww*8 + jx + 4; if (xx >= W) xx -= W;
        const __nv_bfloat16* p = feat + ((size_t)(bb*H + yy)*W + xx)*96;
        uint4 uk = *(const uint4*)(p + 32 + part*8);
        uint4 uv = *(const uint4*)(p + 64 + part*8);
        const __nv_bfloat162* hk = (const __nv_bfloat162*)&uk;
        const __nv_bfloat162* hv = (const __nv_bfloat162*)&uv;
        #pragma unroll
        for (int t = 0; t < 4; t++) {
            float2 fk = __bfloat1622float2(hk[t]);
            float2 fv = __bfloat1622float2(hv[t]);
            sK[j][part*8 + t*2 + 0] = fk.x;
            sK[j][part*8 + t*2 + 1] = fk.y;
            sV[j][part*8 + t*2 + 0] = fv.x;
            sV[j][part*8 + t*2 + 1] = fv.y;
        }
    }
    for (int idx = tid; idx < 225; idx += 64) sPos[idx] = pos[idx];

    float q[32];
    {
        const __nv_bfloat16* fp = feat + ((size_t)(bb*H + y)*W + x)*96;
        #pragma unroll
        for (int part = 0; part < 4; part++) {
            uint4 u = *(const uint4*)(fp + part*8);
            const __nv_bfloat162* h = (const __nv_bfloat162*)&u;
            #pragma unroll
            for (int t = 0; t < 4; t++) {
                float2 f = __bfloat1622float2(h[t]);
                q[part*8 + t*2 + 0] = f.x;
                q[part*8 + t*2 + 1] = f.y;
            }
        }
    }
    __syncthreads();

    const bool mR = (wh == NWIN-1);
    const bool mC = (ww == NWIN-1);
    const float scale = 0.35355339059327373f;
    const int posOff = (7 - iy)*15 + (7 - ix);

    #pragma unroll 1
    for (int h = 0; h < 4; h++) {
        float lg[64];
        float mx = -1e30f;
        #pragma unroll
        for (int j = 0; j < 64; j++) {
            const int jy = j >> 3, jx = j & 7;
            float d = 0.f;
            #pragma unroll
            for (int dd = 0; dd < 8; dd++)
                d = fmaf(q[h*8 + dd], sK[j][h*8 + dd], d);
            float l = d*scale + sPos[jy*15 + jx + posOff];
            bool msk = (mR && ((iy >= 4) != (jy >= 4))) ||
                       (mC && ((ix >= 4) != (jx >= 4)));
            l = msk ? -1e30f : l;
            lg[j] = l;
            mx = fmaxf(mx, l);
        }
        float s = 0.f;
        #pragma unroll
        for (int j = 0; j < 64; j++) {
            float e = __expf(lg[j] - mx);
            lg[j] = e;
            s += e;
        }
        const float inv = 1.f / s;
        float oh[8];
        #pragma unroll
        for (int dd = 0; dd < 8; dd++) oh[dd] = 0.f;
        #pragma unroll
        for (int j = 0; j < 64; j++) {
            float p = lg[j];
            #pragma unroll
            for (int dd = 0; dd < 8; dd++)
                oh[dd] = fmaf(p, sV[j][h*8 + dd], oh[dd]);
        }
        #pragma unroll
        for (int dd = 0; dd < 8; dd++)
            aout[((size_t)(bb*32 + h*8 + dd)*H + sy)*W + sx] = oh[dd]*inv;
    }
}

// =====================================================================
// output conv (32->3) + roll(+4,+4) + residual  (fp32, unchanged)
// =====================================================================
#define TXO 16
#define TYO 8
#define NTO (TXO*TYO)
__global__ __launch_bounds__(NTO)
void conv_out_k(const float* __restrict__ in, const float* __restrict__ wt,
                const float* __restrict__ bias, const float* __restrict__ xin,
                float* __restrict__ out)
{
    constexpr int CIN = 32, COUT = 3, CHUNK = 16;
    __shared__ float sInb[CHUNK][TYO+2][TXO+2];
    __shared__ float sWb[COUT][CHUNK][9];

    const int bx = blockIdx.x * TXO, by = blockIdx.y * TYO, bb = blockIdx.z;
    const int tid = threadIdx.x;
    const int lx = tid % TXO, ly = tid / TXO;

    float acc[COUT];
    #pragma unroll
    for (int co = 0; co < COUT; co++) acc[co] = __ldg(&bias[co]);

    for (int c0 = 0; c0 < CIN; c0 += CHUNK) {
        __syncthreads();
        for (int idx = tid; idx < COUT*CHUNK*9; idx += NTO) {
            int co = idx / (CHUNK*9);
            int r  = idx - co*(CHUNK*9);
            int ci = r / 9;
            int t  = r - ci*9;
            sWb[co][ci][t] = wt[(co*CIN + c0 + ci)*9 + t];
        }
        {
            const int ty = tid >> 5, tx = tid & 31;
            for (int ci = 0; ci < CHUNK; ci++)
                for (int yy = ty; yy < TYO+2; yy += 4)
                    for (int xx = tx; xx < TXO+2; xx += 32) {
                        int gy = by + yy - 1, gx = bx + xx - 1;
                        float v = 0.f;
                        if ((unsigned)gy < (unsigned)H && (unsigned)gx < (unsigned)W)
                            v = in[((size_t)(bb*CIN + c0 + ci)*H + gy)*W + gx];
                        sInb[ci][yy][xx] = v;
                    }
        }
        __syncthreads();

        #pragma unroll 2
        for (int ci = 0; ci < CHUNK; ci++) {
            float r00 = sInb[ci][ly+0][lx+0], r01 = sInb[ci][ly+0][lx+1], r02 = sInb[ci][ly+0][lx+2];
            float r10 = sInb[ci][ly+1][lx+0], r11 = sInb[ci][ly+1][lx+1], r12 = sInb[ci][ly+1][lx+2];
            float r20 = sInb[ci][ly+2][lx+0], r21 = sInb[ci][ly+2][lx+1], r22 = sInb[ci][ly+2][lx+2];
            #pragma unroll
            for (int co = 0; co < COUT; co++) {
                const float* wp = &sWb[co][ci][0];
                float a = acc[co];
                a = fmaf(r00, wp[0], a);
                a = fmaf(r01, wp[1], a);
                a = fmaf(r02, wp[2], a);
                a = fmaf(r10, wp[3], a);
                a = fmaf(r11, wp[4], a);
                a = fmaf(r12, wp[5], a);
                a = fmaf(r20, wp[6], a);
                a = fmaf(r21, wp[7], a);
                a = fmaf(r22, wp[8], a);
                acc[co] = a;
            }
        }
    }

    const int gy = by + ly, gx = bx + lx;
    int oy = gy + 4; if (oy >= H) oy -= H;
    int ox = gx + 4; if (ox >= W) ox -= W;
    #pragma unroll
    for (int co = 0; co < COUT; co++) {
        size_t idx = ((size_t)(bb*COUT + co)*H + oy)*W + ox;
        out[idx] = xin[idx] + acc[co];
    }
}

// ---------------- launcher ----------------
extern "C" void kernel_launch(void* const* d_in, const int* in_sizes, int n_in,
                              void* d_out, int out_size)
{
    (void)in_sizes; (void)n_in; (void)out_size;
    const float* x   = (const float*)d_in[0];
    const float* wo  = (const float*)d_in[19];
    const float* bo  = (const float*)d_in[20];
    const float* pos = (const float*)d_in[21];
    float* out = (float*)d_out;

    __nv_bfloat16 *h1, *h2, *feat;
    float *aout, *bf1;
    uint32_t *bf2, *bf3;
    cudaGetSymbolAddress((void**)&h1,   g_h1);
    cudaGetSymbolAddress((void**)&h2,   g_h2);
    cudaGetSymbolAddress((void**)&feat, g_feat);
    cudaGetSymbolAddress((void**)&aout, g_aout);
    cudaGetSymbolAddress((void**)&bf1,  g_bf1);
    cudaGetSymbolAddress((void**)&bf2,  g_bf2);
    cudaGetSymbolAddress((void**)&bf3,  g_bf3);

    constexpr int SM1 = 4*130*12*4;

    // B prep
    prep_b1_k<<<dim3(18, 3), 256>>>(
        (const float*)d_in[1], (const float*)d_in[7],  (const float*)d_in[13], bf1);
    prep_b2_k<2, 2, 64><<<dim3(36, 3), 256>>>(
        (const float*)d_in[3], (const float*)d_in[9],  (const float*)d_in[15], bf2);
    prep_b2_k<2, 1, 32><<<dim3(18, 3), 256>>>(
        (const float*)d_in[5], (const float*)d_in[11], (const float*)d_in[17], bf3);

    dim3 gg(W/128, H/2, BATCH*3);   // z = br*2 + bb
    conv1_gemm_k<<<gg, 256, SM1>>>(
        x, bf1,
        (const float*)d_in[2], (const float*)d_in[8], (const float*)d_in[14], h1);
    gemm_bf16_k<2, 2, 64, 32, true,  false><<<gg, 256, SMB>>>(
        h1, bf2,
        (const float*)d_in[4], (const float*)d_in[10], (const float*)d_in[16],
        h2, H1SZ, H2SZ);
    gemm_bf16_k<2, 1, 32, 96, false, true ><<<gg, 256, SMB>>>(
        h2, bf3,
        (const float*)d_in[6], (const float*)d_in[12], (const float*)d_in[18],
        feat, H2SZ, 0);

    attn_k<<<dim3(NWIN*NWIN, BATCH), 64>>>(feat, pos, aout);
    conv_out_k<<<dim3(W/TXO, H/TYO, BATCH), NTO>>>(aout, wo, bo, x, out);
}

// round 10
// speedup vs baseline: 1.8525x; 1.2489x over previous
#include <cuda_runtime.h>
#include <cuda_bf16.h>
#include <cstdint>
#include <cstddef>

#define H 384
#define W 384
#define BATCH 2
#define NWIN 48

#define H1SZ ((size_t)BATCH*H*W*64)   // elements per branch (bf16)
#define H2SZ ((size_t)BATCH*H*W*32)

// ---------------- scratch ----------------
__device__ __nv_bfloat16 g_h1[3*H1SZ];
__device__ __nv_bfloat16 g_h2[3*H2SZ];
__device__ __nv_bfloat16 g_feat[(size_t)BATCH*H*W*96];
__device__ __nv_bfloat16 g_aout[(size_t)BATCH*32*H*W];
__device__ uint32_t g_bf1[3*1024];     // conv1 B frags (bf16x2, im2col K=32)
__device__ uint32_t g_bf2[3*9216];     // conv2 B frags
__device__ uint32_t g_bf3[3*4608];     // conv3 B frags

// ---------------- helpers ----------------
__device__ __forceinline__ void mma_bf16(float& c0, float& c1, float& c2, float& c3,
                                         uint32_t a0, uint32_t a1, uint32_t a2, uint32_t a3,
                                         uint32_t b0, uint32_t b1) {
    asm volatile("mma.sync.aligned.m16n8k16.row.col.f32.bf16.bf16.f32 "
                 "{%0,%1,%2,%3}, {%4,%5,%6,%7}, {%8,%9}, {%0,%1,%2,%3};"
                 : "+f"(c0), "+f"(c1), "+f"(c2), "+f"(c3)
                 : "r"(a0), "r"(a1), "r"(a2), "r"(a3), "r"(b0), "r"(b1));
}
__device__ __forceinline__ void ldmA(uint32_t& r0, uint32_t& r1, uint32_t& r2, uint32_t& r3,
                                     uint32_t addr) {
    asm volatile("ldmatrix.sync.aligned.m8n8.x4.shared.b16 {%0,%1,%2,%3}, [%4];"
                 : "=r"(r0), "=r"(r1), "=r"(r2), "=r"(r3) : "r"(addr));
}
__device__ __forceinline__ uint32_t smem_u32(const void* p) {
    return (uint32_t)__cvta_generic_to_shared(p);
}
__device__ __forceinline__ void cp16(uint32_t dst, const void* src, int sz) {
    asm volatile("cp.async.cg.shared.global [%0], [%1], 16, %2;"
                 :: "r"(dst), "l"(src), "r"(sz));
}
__device__ __forceinline__ void cp4(uint32_t dst, const void* src, int sz) {
    asm volatile("cp.async.ca.shared.global [%0], [%1], 4, %2;"
                 :: "r"(dst), "l"(src), "r"(sz));
}
__device__ __forceinline__ void cp_commit_wait() {
    asm volatile("cp.async.commit_group;");
    asm volatile("cp.async.wait_group 0;");
}

// =====================================================================
// conv1 B prep (bf16x2, im2col K=32: k = ci*9 + dy*3 + dx, 27 real)
// idx = kk*512 + half*128 + lane*4 + r ; n = half*2 + (r>>1), breg = r&1
// k0 = kk*16 + (lane&3)*2 + breg*8 ; co = n*8 + (lane>>2)
// =====================================================================
__global__ void prep_b1_k(const float* __restrict__ w0, const float* __restrict__ w1,
                          const float* __restrict__ w2, uint32_t* __restrict__ outBase)
{
    constexpr int SZ = 1024;
    int idx = blockIdx.x*256 + threadIdx.x;
    if (idx >= SZ) return;
    const float* wt = blockIdx.y == 0 ? w0 : (blockIdx.y == 1 ? w1 : w2);
    uint32_t* outp = outBase + blockIdx.y*SZ;
    int r    = idx & 3;
    int lane = (idx >> 2) & 31;
    int half = (idx >> 7) & 3;
    int kk   = idx >> 9;
    int n    = half*2 + (r >> 1);
    int breg = r & 1;
    int k0 = kk*16 + (lane & 3)*2 + breg*8;
    int co = n*8 + (lane >> 2);
    float v0 = 0.f, v1 = 0.f;
    if (k0 + 0 < 27) v0 = wt[(co*3 + (k0+0)/9)*9 + (k0+0)%9];
    if (k0 + 1 < 27) v1 = wt[(co*3 + (k0+1)/9)*9 + (k0+1)%9];
    __nv_bfloat162 pk = __floats2bfloat162_rn(v0, v1);
    outp[idx] = *(uint32_t*)&pk;
}

// =====================================================================
// bf16 B prep (conv2/conv3) — unchanged layout from R9
// =====================================================================
template<int KSTEPS, int NCHUNK, int CINREAL>
__global__ void prep_b2_k(const float* __restrict__ w0, const float* __restrict__ w1,
                          const float* __restrict__ w2, uint32_t* __restrict__ outBase)
{
    constexpr int SZ = NCHUNK*9*KSTEPS*256;
    int idx = blockIdx.x*256 + threadIdx.x;
    if (idx >= SZ) return;
    const float* wt = blockIdx.y == 0 ? w0 : (blockIdx.y == 1 ? w1 : w2);
    uint32_t* outp = outBase + blockIdx.y*SZ;
    int r    = idx & 3;
    int lane = (idx >> 2) & 31;
    int half = (idx >> 7) & 1;
    int rest = idx >> 8;
    int kk   = rest % KSTEPS;
    int rest2 = rest / KSTEPS;
    int dydx = rest2 % 9;
    int ch   = rest2 / 9;
    int n    = half*2 + (r >> 1);
    int breg = r & 1;
    int ci = ch*32 + kk*16 + (lane & 3)*2 + breg*8;
    int co = n*8 + (lane >> 2);
    __nv_bfloat162 pk = __floats2bfloat162_rn(
        wt[(co*CINREAL + ci + 0)*9 + dydx],
        wt[(co*CINREAL + ci + 1)*9 + dydx]);
    outp[idx] = *(uint32_t*)&pk;
}

// =====================================================================
// conv1: 3->64 via im2col-in-smem bf16 GEMM, K=32 (27 real).
// block 256 thr, tile 2 rows x 128 px. z = br*2 + bb.
// =====================================================================
#define PADB 40

__global__ __launch_bounds__(256, 2)
void conv1_im2col_k(const float* __restrict__ in, const uint32_t* __restrict__ gB,
                    const float* __restrict__ bias0, const float* __restrict__ bias1,
                    const float* __restrict__ bias2, __nv_bfloat16* __restrict__ out)
{
    __shared__ float sRaw[3][4][132];
    __shared__ __align__(16) __nv_bfloat16 sA[256][PADB];

    const int z  = blockIdx.z;
    const int bb = z & 1;
    const int br = z >> 1;
    const float* bias = br == 0 ? bias0 : (br == 1 ? bias1 : bias2);
    gB  += br * 1024;
    out += (size_t)br * H1SZ;

    const int x0 = blockIdx.x * 128;
    const int y0 = blockIdx.y * 2;
    const int tid = threadIdx.x;
    const int warp = tid >> 5, lane = tid & 31;
    const int warpRow = warp >> 2;
    const int pxBase  = (warp & 3) * 32;
    const int groupId = lane >> 2, quad = lane & 3;

    // ---- raw 3-plane tile fill via cp.async (rows y0-1..y0+2, px x0-1..x0+128)
    for (int i = tid; i < 3*4*130; i += 256) {
        int ci = i / 520;
        int r2 = i - ci*520;
        int rr = r2 / 130;
        int xx = r2 - rr*130;
        int y = y0 - 1 + rr, x = x0 - 1 + xx;
        bool inb = ((unsigned)y < (unsigned)H) && ((unsigned)x < (unsigned)W);
        const float* src = in + ((size_t)(bb*3 + ci)*H + (inb ? y : 0))*W + (inb ? x : 0);
        cp4(smem_u32(&sRaw[ci][rr][xx]), src, inb ? 4 : 0);
    }
    cp_commit_wait();
    __syncthreads();

    // ---- im2col build: each thread owns one pixel (row = tid)
    {
        int r = tid >> 7, px = tid & 127;
        float vals[32];
        #pragma unroll
        for (int ci = 0; ci < 3; ci++)
            #pragma unroll
            for (int dy = 0; dy < 3; dy++)
                #pragma unroll
                for (int dx = 0; dx < 3; dx++)
                    vals[ci*9 + dy*3 + dx] = sRaw[ci][r + dy][px + dx];
        #pragma unroll
        for (int k = 27; k < 32; k++) vals[k] = 0.f;
        uint32_t pk[16];
        #pragma unroll
        for (int t = 0; t < 16; t++) {
            __nv_bfloat162 p = __floats2bfloat162_rn(vals[2*t], vals[2*t+1]);
            pk[t] = *(uint32_t*)&p;
        }
        uint4* dstp = (uint4*)&sA[tid][0];
        dstp[0] = make_uint4(pk[0],  pk[1],  pk[2],  pk[3]);
        dstp[1] = make_uint4(pk[4],  pk[5],  pk[6],  pk[7]);
        dstp[2] = make_uint4(pk[8],  pk[9],  pk[10], pk[11]);
        dstp[3] = make_uint4(pk[12], pk[13], pk[14], pk[15]);
    }
    __syncthreads();

    float acc[2][8][4];
    #pragma unroll
    for (int n = 0; n < 8; n++) {
        float b0 = __ldg(&bias[n*8 + quad*2 + 0]);
        float b1 = __ldg(&bias[n*8 + quad*2 + 1]);
        #pragma unroll
        for (int m = 0; m < 2; m++) {
            acc[m][n][0] = b0; acc[m][n][1] = b1;
            acc[m][n][2] = b0; acc[m][n][3] = b1;
        }
    }

    const uint32_t aLane = smem_u32(sA) +
        (uint32_t)((warpRow*128 + pxBase + (lane & 15))*(PADB*2) + (lane >> 4)*16);
    const uint4* pb4 = (const uint4*)gB + lane;

    #pragma unroll
    for (int kk = 0; kk < 2; kk++) {
        uint4 L0 = __ldg(pb4 + kk*128);
        uint4 L1 = __ldg(pb4 + kk*128 + 32);
        uint4 L2 = __ldg(pb4 + kk*128 + 64);
        uint4 L3 = __ldg(pb4 + kk*128 + 96);
        #pragma unroll
        for (int m = 0; m < 2; m++) {
            uint32_t a0, a1, a2, a3;
            ldmA(a0, a1, a2, a3, aLane + (uint32_t)(m*16*(PADB*2) + kk*32));
            mma_bf16(acc[m][0][0], acc[m][0][1], acc[m][0][2], acc[m][0][3], a0,a1,a2,a3, L0.x, L0.y);
            mma_bf16(acc[m][1][0], acc[m][1][1], acc[m][1][2], acc[m][1][3], a0,a1,a2,a3, L0.z, L0.w);
            mma_bf16(acc[m][2][0], acc[m][2][1], acc[m][2][2], acc[m][2][3], a0,a1,a2,a3, L1.x, L1.y);
            mma_bf16(acc[m][3][0], acc[m][3][1], acc[m][3][2], acc[m][3][3], a0,a1,a2,a3, L1.z, L1.w);
            mma_bf16(acc[m][4][0], acc[m][4][1], acc[m][4][2], acc[m][4][3], a0,a1,a2,a3, L2.x, L2.y);
            mma_bf16(acc[m][5][0], acc[m][5][1], acc[m][5][2], acc[m][5][3], a0,a1,a2,a3, L2.z, L2.w);
            mma_bf16(acc[m][6][0], acc[m][6][1], acc[m][6][2], acc[m][6][3], a0,a1,a2,a3, L3.x, L3.y);
            mma_bf16(acc[m][7][0], acc[m][7][1], acc[m][7][2], acc[m][7][3], a0,a1,a2,a3, L3.z, L3.w);
        }
    }

    const int yOut = y0 + warpRow;
    #pragma unroll
    for (int m = 0; m < 2; m++) {
        #pragma unroll
        for (int hh = 0; hh < 2; hh++) {
            int px = pxBase + m*16 + groupId + hh*8;
            __nv_bfloat16* op = out + ((size_t)(bb*H + yOut)*W + x0 + px)*64 + quad*2;
            #pragma unroll
            for (int n = 0; n < 8; n++) {
                float v0 = fmaxf(acc[m][n][hh*2 + 0], 0.f);
                float v1 = fmaxf(acc[m][n][hh*2 + 1], 0.f);
                *(__nv_bfloat162*)(op + n*8) = __floats2bfloat162_rn(v0, v1);
            }
        }
    }
}

// =====================================================================
// bf16 implicit-GEMM conv (conv2/conv3), cp.async fills. As R9 otherwise.
// =====================================================================
#define SMB (4*130*PADB*2)

template<int KSTEPS, int NCHUNK, int CINTOT, int OSTR, bool RELU, bool FEAT>
__global__ __launch_bounds__(256, 2)
void gemm_bf16_k(const __nv_bfloat16* __restrict__ in, const uint32_t* __restrict__ gB,
                 const float* __restrict__ bias0, const float* __restrict__ bias1,
                 const float* __restrict__ bias2, __nv_bfloat16* __restrict__ out,
                 size_t inStride, size_t outStride)
{
    extern __shared__ __align__(16) char sAb[];
    constexpr int BSZ = NCHUNK*9*KSTEPS*256;

    const int z  = blockIdx.z;
    const int bb = z & 1;
    const int br = z >> 1;
    const float* bias = br == 0 ? bias0 : (br == 1 ? bias1 : bias2);
    in  += (size_t)br * inStride;
    out += (size_t)br * outStride;
    gB  += br * BSZ;
    const int outOff = FEAT ? br*32 : 0;

    const int x0 = blockIdx.x * 128;
    const int y0 = blockIdx.y * 2;
    const int tid = threadIdx.x;
    const int warp = tid >> 5, lane = tid & 31;
    const int warpRow = warp >> 2;
    const int pxBase  = (warp & 3) * 32;
    const int groupId = lane >> 2, quad = lane & 3;

    const uint32_t aLane = smem_u32(sAb) + (uint32_t)((lane & 15)*(PADB*2) + (lane >> 4)*16);

    float acc[2][4][4];
    #pragma unroll
    for (int n = 0; n < 4; n++) {
        float b0 = __ldg(&bias[n*8 + quad*2 + 0]);
        float b1 = __ldg(&bias[n*8 + quad*2 + 1]);
        #pragma unroll
        for (int m = 0; m < 2; m++) {
            acc[m][n][0] = b0; acc[m][n][1] = b1;
            acc[m][n][2] = b0; acc[m][n][3] = b1;
        }
    }

    #pragma unroll 1
    for (int ch = 0; ch < NCHUNK; ch++) {
        __syncthreads();
        #pragma unroll
        for (int r = 0; r < 4; r++) {
            int y = y0 - 1 + r;
            bool yin = (unsigned)y < (unsigned)H;
            for (int i = tid; i < 130*4; i += 256) {
                int px = i >> 2, v = i & 3;
                int x = x0 - 1 + px;
                bool inb = yin && ((unsigned)x < (unsigned)W);
                const __nv_bfloat16* src = in +
                    ((size_t)(bb*H + (inb ? y : 0))*W + (inb ? x : 0))*CINTOT + ch*32 + v*8;
                cp16(smem_u32(sAb + (size_t)(r*130 + px)*(PADB*2) + v*16), src, inb ? 16 : 0);
            }
        }
        cp_commit_wait();
        __syncthreads();

        #pragma unroll
        for (int dy = 0; dy < 3; dy++) {
            #pragma unroll
            for (int dx = 0; dx < 3; dx++) {
                const uint32_t aBase = aLane +
                    (uint32_t)(((warpRow + dy)*130 + pxBase + dx)*(PADB*2));
                const uint4* pb4 = (const uint4*)gB + ((ch*9 + dy*3 + dx)*KSTEPS)*64 + lane;
                #pragma unroll
                for (int kk = 0; kk < KSTEPS; kk++) {
                    uint4 L0 = __ldg(pb4 + kk*64);
                    uint4 L1 = __ldg(pb4 + kk*64 + 32);
                    #pragma unroll
                    for (int m = 0; m < 2; m++) {
                        uint32_t a0, a1, a2, a3;
                        ldmA(a0, a1, a2, a3, aBase + (uint32_t)(m*16*(PADB*2) + kk*32));
                        mma_bf16(acc[m][0][0], acc[m][0][1], acc[m][0][2], acc[m][0][3],
                                 a0, a1, a2, a3, L0.x, L0.y);
                        mma_bf16(acc[m][1][0], acc[m][1][1], acc[m][1][2], acc[m][1][3],
                                 a0, a1, a2, a3, L0.z, L0.w);
                        mma_bf16(acc[m][2][0], acc[m][2][1], acc[m][2][2], acc[m][2][3],
                                 a0, a1, a2, a3, L1.x, L1.y);
                        mma_bf16(acc[m][3][0], acc[m][3][1], acc[m][3][2], acc[m][3][3],
                                 a0, a1, a2, a3, L1.z, L1.w);
                    }
                }
            }
        }
    }

    const int yOut = y0 + warpRow;
    #pragma unroll
    for (int m = 0; m < 2; m++) {
        #pragma unroll
        for (int hh = 0; hh < 2; hh++) {
            int px = pxBase + m*16 + groupId + hh*8;
            __nv_bfloat16* op = out + ((size_t)(bb*H + yOut)*W + x0 + px)*OSTR + outOff + quad*2;
            #pragma unroll
            for (int n = 0; n < 4; n++) {
                float v0 = acc[m][n][hh*2 + 0];
                float v1 = acc[m][n][hh*2 + 1];
                if (RELU) { v0 = fmaxf(v0, 0.f); v1 = fmaxf(v1, 0.f); }
                *(__nv_bfloat162*)(op + n*8) = __floats2bfloat162_rn(v0, v1);
            }
        }
    }
}

// =====================================================================
// shifted-window attention (bf16 feat in, bf16 aout out, fp32 math)
// =====================================================================
__global__ __launch_bounds__(64)
void attn_k(const __nv_bfloat16* __restrict__ feat, const float* __restrict__ pos,
            __nv_bfloat16* __restrict__ aout)
{
    __shared__ float sK[64][32];
    __shared__ float sV[64][32];
    __shared__ float sPos[225];

    const int w  = blockIdx.x, bb = blockIdx.y;
    const int wh = w / NWIN, ww = w - wh*NWIN;
    const int tid = threadIdx.x;
    const int iy = tid >> 3, ix = tid & 7;
    const int sy = wh*8 + iy, sx = ww*8 + ix;
    int y = sy + 4; if (y >= H) y -= H;
    int x = sx + 4; if (x >= W) x -= W;

    for (int idx = tid; idx < 64*4; idx += 64) {
        int j = idx >> 2, part = idx & 3;
        int jy = j >> 3, jx = j & 7;
        int yy = wh*8 + jy + 4; if (yy >= H) yy -= H;
        int xx = ww*8 + jx + 4; if (xx >= W) xx -= W;
        const __nv_bfloat16* p = feat + ((size_t)(bb*H + yy)*W + xx)*96;
        uint4 uk = *(const uint4*)(p + 32 + part*8);
        uint4 uv = *(const uint4*)(p + 64 + part*8);
        const __nv_bfloat162* hk = (const __nv_bfloat162*)&uk;
        const __nv_bfloat162* hv = (const __nv_bfloat162*)&uv;
        #pragma unroll
        for (int t = 0; t < 4; t++) {
            float2 fk = __bfloat1622float2(hk[t]);
            float2 fv = __bfloat1622float2(hv[t]);
            sK[j][part*8 + t*2 + 0] = fk.x;
            sK[j][part*8 + t*2 + 1] = fk.y;
            sV[j][part*8 + t*2 + 0] = fv.x;
            sV[j][part*8 + t*2 + 1] = fv.y;
        }
    }
    for (int idx = tid; idx < 225; idx += 64) sPos[idx] = pos[idx];

    float q[32];
    {
        const __nv_bfloat16* fp = feat + ((size_t)(bb*H + y)*W + x)*96;
        #pragma unroll
        for (int part = 0; part < 4; part++) {
            uint4 u = *(const uint4*)(fp + part*8);
            const __nv_bfloat162* hq = (const __nv_bfloat162*)&u;
            #pragma unroll
            for (int t = 0; t < 4; t++) {
                float2 f = __bfloat1622float2(hq[t]);
                q[part*8 + t*2 + 0] = f.x;
                q[part*8 + t*2 + 1] = f.y;
            }
        }
    }
    __syncthreads();

    const bool mR = (wh == NWIN-1);
    const bool mC = (ww == NWIN-1);
    const float scale = 0.35355339059327373f;
    const int posOff = (7 - iy)*15 + (7 - ix);

    #pragma unroll 1
    for (int h = 0; h < 4; h++) {
        float lg[64];
        float mx = -1e30f;
        #pragma unroll
        for (int j = 0; j < 64; j++) {
            const int jy = j >> 3, jx = j & 7;
            float d = 0.f;
            #pragma unroll
            for (int dd = 0; dd < 8; dd++)
                d = fmaf(q[h*8 + dd], sK[j][h*8 + dd], d);
            float l = d*scale + sPos[jy*15 + jx + posOff];
            bool msk = (mR && ((iy >= 4) != (jy >= 4))) ||
                       (mC && ((ix >= 4) != (jx >= 4)));
            l = msk ? -1e30f : l;
            lg[j] = l;
            mx = fmaxf(mx, l);
        }
        float s = 0.f;
        #pragma unroll
        for (int j = 0; j < 64; j++) {
            float e = __expf(lg[j] - mx);
            lg[j] = e;
            s += e;
        }
        const float inv = 1.f / s;
        float oh[8];
        #pragma unroll
        for (int dd = 0; dd < 8; dd++) oh[dd] = 0.f;
        #pragma unroll
        for (int j = 0; j < 64; j++) {
            float p = lg[j];
            #pragma unroll
            for (int dd = 0; dd < 8; dd++)
                oh[dd] = fmaf(p, sV[j][h*8 + dd], oh[dd]);
        }
        #pragma unroll
        for (int dd = 0; dd < 8; dd++)
            aout[((size_t)(bb*32 + h*8 + dd)*H + sy)*W + sx] = __float2bfloat16(oh[dd]*inv);
    }
}

// =====================================================================
// output conv (32->3) + roll(+4,+4) + residual (bf16 in, fp32 math/out)
// =====================================================================
#define TXO 16
#define TYO 8
#define NTO (TXO*TYO)
__global__ __launch_bounds__(NTO)
void conv_out_k(const __nv_bfloat16* __restrict__ in, const float* __restrict__ wt,
                const float* __restrict__ bias, const float* __restrict__ xin,
                float* __restrict__ out)
{
    constexpr int CIN = 32, COUT = 3, CHUNK = 16;
    __shared__ float sInb[CHUNK][TYO+2][TXO+2];
    __shared__ float sWb[COUT][CHUNK][9];

    const int bx = blockIdx.x * TXO, by = blockIdx.y * TYO, bb = blockIdx.z;
    const int tid = threadIdx.x;
    const int lx = tid % TXO, ly = tid / TXO;

    float acc[COUT];
    #pragma unroll
    for (int co = 0; co < COUT; co++) acc[co] = __ldg(&bias[co]);

    for (int c0 = 0; c0 < CIN; c0 += CHUNK) {
        __syncthreads();
        for (int idx = tid; idx < COUT*CHUNK*9; idx += NTO) {
            int co = idx / (CHUNK*9);
            int r  = idx - co*(CHUNK*9);
            int ci = r / 9;
            int t  = r - ci*9;
            sWb[co][ci][t] = wt[(co*CIN + c0 + ci)*9 + t];
        }
        {
            const int ty = tid >> 5, tx = tid & 31;
            for (int ci = 0; ci < CHUNK; ci++)
                for (int yy = ty; yy < TYO+2; yy += 4)
                    for (int xx = tx; xx < TXO+2; xx += 32) {
                        int gy = by + yy - 1, gx = bx + xx - 1;
                        float v = 0.f;
                        if ((unsigned)gy < (unsigned)H && (unsigned)gx < (unsigned)W)
                            v = __bfloat162float(in[((size_t)(bb*CIN + c0 + ci)*H + gy)*W + gx]);
                        sInb[ci][yy][xx] = v;
                    }
        }
        __syncthreads();

        #pragma unroll 2
        for (int ci = 0; ci < CHUNK; ci++) {
            float r00 = sInb[ci][ly+0][lx+0], r01 = sInb[ci][ly+0][lx+1], r02 = sInb[ci][ly+0][lx+2];
            float r10 = sInb[ci][ly+1][lx+0], r11 = sInb[ci][ly+1][lx+1], r12 = sInb[ci][ly+1][lx+2];
            float r20 = sInb[ci][ly+2][lx+0], r21 = sInb[ci][ly+2][lx+1], r22 = sInb[ci][ly+2][lx+2];
            #pragma unroll
            for (int co = 0; co < COUT; co++) {
                const float* wp = &sWb[co][ci][0];
                float a = acc[co];
                a = fmaf(r00, wp[0], a);
                a = fmaf(r01, wp[1], a);
                a = fmaf(r02, wp[2], a);
                a = fmaf(r10, wp[3], a);
                a = fmaf(r11, wp[4], a);
                a = fmaf(r12, wp[5], a);
                a = fmaf(r20, wp[6], a);
                a = fmaf(r21, wp[7], a);
                a = fmaf(r22, wp[8], a);
                acc[co] = a;
            }
        }
    }

    const int gy = by + ly, gx = bx + lx;
    int oy = gy + 4; if (oy >= H) oy -= H;
    int ox = gx + 4; if (ox >= W) ox -= W;
    #pragma unroll
    for (int co = 0; co < COUT; co++) {
        size_t idx = ((size_t)(bb*COUT + co)*H + oy)*W + ox;
        out[idx] = xin[idx] + acc[co];
    }
}

// ---------------- launcher ----------------
extern "C" void kernel_launch(void* const* d_in, const int* in_sizes, int n_in,
                              void* d_out, int out_size)
{
    (void)in_sizes; (void)n_in; (void)out_size;
    const float* x   = (const float*)d_in[0];
    const float* wo  = (const float*)d_in[19];
    const float* bo  = (const float*)d_in[20];
    const float* pos = (const float*)d_in[21];
    float* out = (float*)d_out;

    __nv_bfloat16 *h1, *h2, *feat, *aout;
    uint32_t *bf1, *bf2, *bf3;
    cudaGetSymbolAddress((void**)&h1,   g_h1);
    cudaGetSymbolAddress((void**)&h2,   g_h2);
    cudaGetSymbolAddress((void**)&feat, g_feat);
    cudaGetSymbolAddress((void**)&aout, g_aout);
    cudaGetSymbolAddress((void**)&bf1,  g_bf1);
    cudaGetSymbolAddress((void**)&bf2,  g_bf2);
    cudaGetSymbolAddress((void**)&bf3,  g_bf3);

    // B prep
    prep_b1_k<<<dim3(4, 3), 256>>>(
        (const float*)d_in[1], (const float*)d_in[7],  (const float*)d_in[13], bf1);
    prep_b2_k<2, 2, 64><<<dim3(36, 3), 256>>>(
        (const float*)d_in[3], (const float*)d_in[9],  (const float*)d_in[15], bf2);
    prep_b2_k<2, 1, 32><<<dim3(18, 3), 256>>>(
        (const float*)d_in[5], (const float*)d_in[11], (const float*)d_in[17], bf3);

    dim3 gg(W/128, H/2, BATCH*3);   // z = br*2 + bb
    conv1_im2col_k<<<gg, 256>>>(
        x, bf1,
        (const float*)d_in[2], (const float*)d_in[8], (const float*)d_in[14], h1);
    gemm_bf16_k<2, 2, 64, 32, true,  false><<<gg, 256, SMB>>>(
        h1, bf2,
        (const float*)d_in[4], (const float*)d_in[10], (const float*)d_in[16],
        h2, H1SZ, H2SZ);
    gemm_bf16_k<2, 1, 32, 96, false, true ><<<gg, 256, SMB>>>(
        h2, bf3,
        (const float*)d_in[6], (const float*)d_in[12], (const float*)d_in[18],
        feat, H2SZ, 0);

    attn_k<<<dim3(NWIN*NWIN, BATCH), 64>>>(feat, pos, aout);
    conv_out_k<<<dim3(W/TXO, H/TYO, BATCH), NTO>>>(aout, wo, bo, x, out);
}

// round 11
// speedup vs baseline: 2.0955x; 1.1312x over previous
#include <cuda_runtime.h>
#include <cuda_bf16.h>
#include <cstdint>
#include <cstddef>

#define H 384
#define W 384
#define BATCH 2
#define NWIN 48

#define H1SZ ((size_t)BATCH*H*W*64)   // elements per branch (bf16)
#define H2SZ ((size_t)BATCH*H*W*32)

// ---------------- scratch ----------------
__device__ __nv_bfloat16 g_h1[3*H1SZ];
__device__ __nv_bfloat16 g_h2[3*H2SZ];
__device__ __nv_bfloat16 g_feat[(size_t)BATCH*H*W*96];
__device__ __nv_bfloat16 g_aout[(size_t)BATCH*H*W*32];   // channel-last, shifted space
__device__ uint32_t g_bf1[3*1024];     // conv1 B frags (bf16x2, im2col K=32)
__device__ uint32_t g_bf2[3*9216];     // conv2 B frags
__device__ uint32_t g_bf3[3*4608];     // conv3 B frags
__device__ uint32_t g_bfo[1152];       // conv_out B frags (8 couts, 3 real)

// ---------------- helpers ----------------
__device__ __forceinline__ void mma_bf16(float& c0, float& c1, float& c2, float& c3,
                                         uint32_t a0, uint32_t a1, uint32_t a2, uint32_t a3,
                                         uint32_t b0, uint32_t b1) {
    asm volatile("mma.sync.aligned.m16n8k16.row.col.f32.bf16.bf16.f32 "
                 "{%0,%1,%2,%3}, {%4,%5,%6,%7}, {%8,%9}, {%0,%1,%2,%3};"
                 : "+f"(c0), "+f"(c1), "+f"(c2), "+f"(c3)
                 : "r"(a0), "r"(a1), "r"(a2), "r"(a3), "r"(b0), "r"(b1));
}
__device__ __forceinline__ void ldmA(uint32_t& r0, uint32_t& r1, uint32_t& r2, uint32_t& r3,
                                     uint32_t addr) {
    asm volatile("ldmatrix.sync.aligned.m8n8.x4.shared.b16 {%0,%1,%2,%3}, [%4];"
                 : "=r"(r0), "=r"(r1), "=r"(r2), "=r"(r3) : "r"(addr));
}
__device__ __forceinline__ uint32_t smem_u32(const void* p) {
    return (uint32_t)__cvta_generic_to_shared(p);
}
__device__ __forceinline__ void cp16(uint32_t dst, const void* src, int sz) {
    asm volatile("cp.async.cg.shared.global [%0], [%1], 16, %2;"
                 :: "r"(dst), "l"(src), "r"(sz));
}
__device__ __forceinline__ void cp4(uint32_t dst, const void* src, int sz) {
    asm volatile("cp.async.ca.shared.global [%0], [%1], 4, %2;"
                 :: "r"(dst), "l"(src), "r"(sz));
}
__device__ __forceinline__ void cp_commit_wait() {
    asm volatile("cp.async.commit_group;");
    asm volatile("cp.async.wait_group 0;");
}

// =====================================================================
// conv1 B prep (bf16x2, im2col K=32: k = ci*9 + dy*3 + dx, 27 real)
// =====================================================================
__global__ void prep_b1_k(const float* __restrict__ w0, const float* __restrict__ w1,
                          const float* __restrict__ w2, uint32_t* __restrict__ outBase)
{
    constexpr int SZ = 1024;
    int idx = blockIdx.x*256 + threadIdx.x;
    if (idx >= SZ) return;
    const float* wt = blockIdx.y == 0 ? w0 : (blockIdx.y == 1 ? w1 : w2);
    uint32_t* outp = outBase + blockIdx.y*SZ;
    int r    = idx & 3;
    int lane = (idx >> 2) & 31;
    int half = (idx >> 7) & 3;
    int kk   = idx >> 9;
    int n    = half*2 + (r >> 1);
    int breg = r & 1;
    int k0 = kk*16 + (lane & 3)*2 + breg*8;
    int co = n*8 + (lane >> 2);
    float v0 = 0.f, v1 = 0.f;
    if (k0 + 0 < 27) v0 = wt[(co*3 + (k0+0)/9)*9 + (k0+0)%9];
    if (k0 + 1 < 27) v1 = wt[(co*3 + (k0+1)/9)*9 + (k0+1)%9];
    __nv_bfloat162 pk = __floats2bfloat162_rn(v0, v1);
    outp[idx] = *(uint32_t*)&pk;
}

// =====================================================================
// bf16 B prep (conv2/conv3)
// =====================================================================
template<int KSTEPS, int NCHUNK, int CINREAL>
__global__ void prep_b2_k(const float* __restrict__ w0, const float* __restrict__ w1,
                          const float* __restrict__ w2, uint32_t* __restrict__ outBase)
{
    constexpr int SZ = NCHUNK*9*KSTEPS*256;
    int idx = blockIdx.x*256 + threadIdx.x;
    if (idx >= SZ) return;
    const float* wt = blockIdx.y == 0 ? w0 : (blockIdx.y == 1 ? w1 : w2);
    uint32_t* outp = outBase + blockIdx.y*SZ;
    int r    = idx & 3;
    int lane = (idx >> 2) & 31;
    int half = (idx >> 7) & 1;
    int rest = idx >> 8;
    int kk   = rest % KSTEPS;
    int rest2 = rest / KSTEPS;
    int dydx = rest2 % 9;
    int ch   = rest2 / 9;
    int n    = half*2 + (r >> 1);
    int breg = r & 1;
    int ci = ch*32 + kk*16 + (lane & 3)*2 + breg*8;
    int co = n*8 + (lane >> 2);
    __nv_bfloat162 pk = __floats2bfloat162_rn(
        wt[(co*CINREAL + ci + 0)*9 + dydx],
        wt[(co*CINREAL + ci + 1)*9 + dydx]);
    outp[idx] = *(uint32_t*)&pk;
}

// =====================================================================
// conv_out B prep: wt (3,32,3,3), 8 couts (3 real, rest 0)
// idx = (dydx*2 + kk)*64 + lane*2 + breg
// =====================================================================
__global__ void prep_bo_k(const float* __restrict__ wt, uint32_t* __restrict__ outp)
{
    int idx = blockIdx.x*256 + threadIdx.x;
    if (idx >= 1152) return;
    int breg = idx & 1;
    int lane = (idx >> 1) & 31;
    int kk   = (idx >> 6) & 1;
    int dydx = idx >> 7;
    int ci = kk*16 + (lane & 3)*2 + breg*8;
    int co = lane >> 2;
    float v0 = 0.f, v1 = 0.f;
    if (co < 3) {
        v0 = wt[(co*32 + ci + 0)*9 + dydx];
        v1 = wt[(co*32 + ci + 1)*9 + dydx];
    }
    __nv_bfloat162 pk = __floats2bfloat162_rn(v0, v1);
    outp[idx] = *(uint32_t*)&pk;
}

// =====================================================================
// conv1 fused: 3->64 x 3 branches. One fill + one im2col, 3 mainloops.
// block 256 thr, tile 2 rows x 128 px. z = bb.
// =====================================================================
#define PADB 40

__global__ __launch_bounds__(256, 2)
void conv1_im2col_k(const float* __restrict__ in, const uint32_t* __restrict__ gB,
                    const float* __restrict__ bias0, const float* __restrict__ bias1,
                    const float* __restrict__ bias2, __nv_bfloat16* __restrict__ out)
{
    __shared__ float sRaw[3][4][132];
    __shared__ __align__(16) __nv_bfloat16 sA[256][PADB];

    const int bb = blockIdx.z;
    const int x0 = blockIdx.x * 128;
    const int y0 = blockIdx.y * 2;
    const int tid = threadIdx.x;
    const int warp = tid >> 5, lane = tid & 31;
    const int warpRow = warp >> 2;
    const int pxBase  = (warp & 3) * 32;
    const int groupId = lane >> 2, quad = lane & 3;

    // ---- raw 3-plane tile fill via cp.async
    for (int i = tid; i < 3*4*130; i += 256) {
        int ci = i / 520;
        int r2 = i - ci*520;
        int rr = r2 / 130;
        int xx = r2 - rr*130;
        int y = y0 - 1 + rr, x = x0 - 1 + xx;
        bool inb = ((unsigned)y < (unsigned)H) && ((unsigned)x < (unsigned)W);
        const float* src = in + ((size_t)(bb*3 + ci)*H + (inb ? y : 0))*W + (inb ? x : 0);
        cp4(smem_u32(&sRaw[ci][rr][xx]), src, inb ? 4 : 0);
    }
    cp_commit_wait();
    __syncthreads();

    // ---- im2col build (once)
    {
        int r = tid >> 7, px = tid & 127;
        float vals[32];
        #pragma unroll
        for (int ci = 0; ci < 3; ci++)
            #pragma unroll
            for (int dy = 0; dy < 3; dy++)
                #pragma unroll
                for (int dx = 0; dx < 3; dx++)
                    vals[ci*9 + dy*3 + dx] = sRaw[ci][r + dy][px + dx];
        #pragma unroll
        for (int k = 27; k < 32; k++) vals[k] = 0.f;
        uint32_t pk[16];
        #pragma unroll
        for (int t = 0; t < 16; t++) {
            __nv_bfloat162 p = __floats2bfloat162_rn(vals[2*t], vals[2*t+1]);
            pk[t] = *(uint32_t*)&p;
        }
        uint4* dstp = (uint4*)&sA[tid][0];
        dstp[0] = make_uint4(pk[0],  pk[1],  pk[2],  pk[3]);
        dstp[1] = make_uint4(pk[4],  pk[5],  pk[6],  pk[7]);
        dstp[2] = make_uint4(pk[8],  pk[9],  pk[10], pk[11]);
        dstp[3] = make_uint4(pk[12], pk[13], pk[14], pk[15]);
    }
    __syncthreads();

    const uint32_t aLane = smem_u32(sA) +
        (uint32_t)((warpRow*128 + pxBase + (lane & 15))*(PADB*2) + (lane >> 4)*16);
    const int yOut = y0 + warpRow;

    #pragma unroll 1
    for (int br = 0; br < 3; br++) {
        const float* bias = br == 0 ? bias0 : (br == 1 ? bias1 : bias2);
        const uint4* pb4 = (const uint4*)(gB + br*1024) + lane;
        __nv_bfloat16* outp = out + (size_t)br * H1SZ;

        float acc[2][8][4];
        #pragma unroll
        for (int n = 0; n < 8; n++) {
            float b0 = __ldg(&bias[n*8 + quad*2 + 0]);
            float b1 = __ldg(&bias[n*8 + quad*2 + 1]);
            #pragma unroll
            for (int m = 0; m < 2; m++) {
                acc[m][n][0] = b0; acc[m][n][1] = b1;
                acc[m][n][2] = b0; acc[m][n][3] = b1;
            }
        }

        #pragma unroll
        for (int kk = 0; kk < 2; kk++) {
            uint4 L0 = __ldg(pb4 + kk*128);
            uint4 L1 = __ldg(pb4 + kk*128 + 32);
            uint4 L2 = __ldg(pb4 + kk*128 + 64);
            uint4 L3 = __ldg(pb4 + kk*128 + 96);
            #pragma unroll
            for (int m = 0; m < 2; m++) {
                uint32_t a0, a1, a2, a3;
                ldmA(a0, a1, a2, a3, aLane + (uint32_t)(m*16*(PADB*2) + kk*32));
                mma_bf16(acc[m][0][0], acc[m][0][1], acc[m][0][2], acc[m][0][3], a0,a1,a2,a3, L0.x, L0.y);
                mma_bf16(acc[m][1][0], acc[m][1][1], acc[m][1][2], acc[m][1][3], a0,a1,a2,a3, L0.z, L0.w);
                mma_bf16(acc[m][2][0], acc[m][2][1], acc[m][2][2], acc[m][2][3], a0,a1,a2,a3, L1.x, L1.y);
                mma_bf16(acc[m][3][0], acc[m][3][1], acc[m][3][2], acc[m][3][3], a0,a1,a2,a3, L1.z, L1.w);
                mma_bf16(acc[m][4][0], acc[m][4][1], acc[m][4][2], acc[m][4][3], a0,a1,a2,a3, L2.x, L2.y);
                mma_bf16(acc[m][5][0], acc[m][5][1], acc[m][5][2], acc[m][5][3], a0,a1,a2,a3, L2.z, L2.w);
                mma_bf16(acc[m][6][0], acc[m][6][1], acc[m][6][2], acc[m][6][3], a0,a1,a2,a3, L3.x, L3.y);
                mma_bf16(acc[m][7][0], acc[m][7][1], acc[m][7][2], acc[m][7][3], a0,a1,a2,a3, L3.z, L3.w);
            }
        }

        #pragma unroll
        for (int m = 0; m < 2; m++) {
            #pragma unroll
            for (int hh = 0; hh < 2; hh++) {
                int px = pxBase + m*16 + groupId + hh*8;
                __nv_bfloat16* op = outp + ((size_t)(bb*H + yOut)*W + x0 + px)*64 + quad*2;
                #pragma unroll
                for (int n = 0; n < 8; n++) {
                    float v0 = fmaxf(acc[m][n][hh*2 + 0], 0.f);
                    float v1 = fmaxf(acc[m][n][hh*2 + 1], 0.f);
                    *(__nv_bfloat162*)(op + n*8) = __floats2bfloat162_rn(v0, v1);
                }
            }
        }
    }
}

// =====================================================================
// bf16 implicit-GEMM conv (conv2/conv3), cp.async fills.
// =====================================================================
#define SMB (4*130*PADB*2)

template<int KSTEPS, int NCHUNK, int CINTOT, int OSTR, bool RELU, bool FEAT>
__global__ __launch_bounds__(256, 2)
void gemm_bf16_k(const __nv_bfloat16* __restrict__ in, const uint32_t* __restrict__ gB,
                 const float* __restrict__ bias0, const float* __restrict__ bias1,
                 const float* __restrict__ bias2, __nv_bfloat16* __restrict__ out,
                 size_t inStride, size_t outStride)
{
    extern __shared__ __align__(16) char sAb[];
    constexpr int BSZ = NCHUNK*9*KSTEPS*256;

    const int z  = blockIdx.z;
    const int bb = z & 1;
    const int br = z >> 1;
    const float* bias = br == 0 ? bias0 : (br == 1 ? bias1 : bias2);
    in  += (size_t)br * inStride;
    out += (size_t)br * outStride;
    gB  += br * BSZ;
    const int outOff = FEAT ? br*32 : 0;

    const int x0 = blockIdx.x * 128;
    const int y0 = blockIdx.y * 2;
    const int tid = threadIdx.x;
    const int warp = tid >> 5, lane = tid & 31;
    const int warpRow = warp >> 2;
    const int pxBase  = (warp & 3) * 32;
    const int groupId = lane >> 2, quad = lane & 3;

    const uint32_t aLane = smem_u32(sAb) + (uint32_t)((lane & 15)*(PADB*2) + (lane >> 4)*16);

    float acc[2][4][4];
    #pragma unroll
    for (int n = 0; n < 4; n++) {
        float b0 = __ldg(&bias[n*8 + quad*2 + 0]);
        float b1 = __ldg(&bias[n*8 + quad*2 + 1]);
        #pragma unroll
        for (int m = 0; m < 2; m++) {
            acc[m][n][0] = b0; acc[m][n][1] = b1;
            acc[m][n][2] = b0; acc[m][n][3] = b1;
        }
    }

    #pragma unroll 1
    for (int ch = 0; ch < NCHUNK; ch++) {
        __syncthreads();
        #pragma unroll
        for (int r = 0; r < 4; r++) {
            int y = y0 - 1 + r;
            bool yin = (unsigned)y < (unsigned)H;
            for (int i = tid; i < 130*4; i += 256) {
                int px = i >> 2, v = i & 3;
                int x = x0 - 1 + px;
                bool inb = yin && ((unsigned)x < (unsigned)W);
                const __nv_bfloat16* src = in +
                    ((size_t)(bb*H + (inb ? y : 0))*W + (inb ? x : 0))*CINTOT + ch*32 + v*8;
                cp16(smem_u32(sAb + (size_t)(r*130 + px)*(PADB*2) + v*16), src, inb ? 16 : 0);
            }
        }
        cp_commit_wait();
        __syncthreads();

        #pragma unroll
        for (int dy = 0; dy < 3; dy++) {
            #pragma unroll
            for (int dx = 0; dx < 3; dx++) {
                const uint32_t aBase = aLane +
                    (uint32_t)(((warpRow + dy)*130 + pxBase + dx)*(PADB*2));
                const uint4* pb4 = (const uint4*)gB + ((ch*9 + dy*3 + dx)*KSTEPS)*64 + lane;
                #pragma unroll
                for (int kk = 0; kk < KSTEPS; kk++) {
                    uint4 L0 = __ldg(pb4 + kk*64);
                    uint4 L1 = __ldg(pb4 + kk*64 + 32);
                    #pragma unroll
                    for (int m = 0; m < 2; m++) {
                        uint32_t a0, a1, a2, a3;
                        ldmA(a0, a1, a2, a3, aBase + (uint32_t)(m*16*(PADB*2) + kk*32));
                        mma_bf16(acc[m][0][0], acc[m][0][1], acc[m][0][2], acc[m][0][3],
                                 a0, a1, a2, a3, L0.x, L0.y);
                        mma_bf16(acc[m][1][0], acc[m][1][1], acc[m][1][2], acc[m][1][3],
                                 a0, a1, a2, a3, L0.z, L0.w);
                        mma_bf16(acc[m][2][0], acc[m][2][1], acc[m][2][2], acc[m][2][3],
                                 a0, a1, a2, a3, L1.x, L1.y);
                        mma_bf16(acc[m][3][0], acc[m][3][1], acc[m][3][2], acc[m][3][3],
                                 a0, a1, a2, a3, L1.z, L1.w);
                    }
                }
            }
        }
    }

    const int yOut = y0 + warpRow;
    #pragma unroll
    for (int m = 0; m < 2; m++) {
        #pragma unroll
        for (int hh = 0; hh < 2; hh++) {
            int px = pxBase + m*16 + groupId + hh*8;
            __nv_bfloat16* op = out + ((size_t)(bb*H + yOut)*W + x0 + px)*OSTR + outOff + quad*2;
            #pragma unroll
            for (int n = 0; n < 4; n++) {
                float v0 = acc[m][n][hh*2 + 0];
                float v1 = acc[m][n][hh*2 + 1];
                if (RELU) { v0 = fmaxf(v0, 0.f); v1 = fmaxf(v1, 0.f); }
                *(__nv_bfloat162*)(op + n*8) = __floats2bfloat162_rn(v0, v1);
            }
        }
    }
}

// =====================================================================
// shifted-window attention (bf16 feat in, bf16 channel-last aout)
// =====================================================================
__global__ __launch_bounds__(64)
void attn_k(const __nv_bfloat16* __restrict__ feat, const float* __restrict__ pos,
            __nv_bfloat16* __restrict__ aout)
{
    __shared__ float sK[64][32];
    __shared__ float sV[64][32];
    __shared__ float sPos[225];

    const int w  = blockIdx.x, bb = blockIdx.y;
    const int wh = w / NWIN, ww = w - wh*NWIN;
    const int tid = threadIdx.x;
    const int iy = tid >> 3, ix = tid & 7;
    const int sy = wh*8 + iy, sx = ww*8 + ix;
    int y = sy + 4; if (y >= H) y -= H;
    int x = sx + 4; if (x >= W) x -= W;

    for (int idx = tid; idx < 64*4; idx += 64) {
        int j = idx >> 2, part = idx & 3;
        int jy = j >> 3, jx = j & 7;
        int yy = wh*8 + jy + 4; if (yy >= H) yy -= H;
        int xx = ww*8 + jx + 4; if (xx >= W) xx -= W;
        const __nv_bfloat16* p = feat + ((size_t)(bb*H + yy)*W + xx)*96;
        uint4 uk = *(const uint4*)(p + 32 + part*8);
        uint4 uv = *(const uint4*)(p + 64 + part*8);
        const __nv_bfloat162* hk = (const __nv_bfloat162*)&uk;
        const __nv_bfloat162* hv = (const __nv_bfloat162*)&uv;
        #pragma unroll
        for (int t = 0; t < 4; t++) {
            float2 fk = __bfloat1622float2(hk[t]);
            float2 fv = __bfloat1622float2(hv[t]);
            sK[j][part*8 + t*2 + 0] = fk.x;
            sK[j][part*8 + t*2 + 1] = fk.y;
            sV[j][part*8 + t*2 + 0] = fv.x;
            sV[j][part*8 + t*2 + 1] = fv.y;
        }
    }
    for (int idx = tid; idx < 225; idx += 64) sPos[idx] = pos[idx];

    float q[32];
    {
        const __nv_bfloat16* fp = feat + ((size_t)(bb*H + y)*W + x)*96;
        #pragma unroll
        for (int part = 0; part < 4; part++) {
            uint4 u = *(const uint4*)(fp + part*8);
            const __nv_bfloat162* hq = (const __nv_bfloat162*)&u;
            #pragma unroll
            for (int t = 0; t < 4; t++) {
                float2 f = __bfloat1622float2(hq[t]);
                q[part*8 + t*2 + 0] = f.x;
                q[part*8 + t*2 + 1] = f.y;
            }
        }
    }
    __syncthreads();

    const bool mR = (wh == NWIN-1);
    const bool mC = (ww == NWIN-1);
    const float scale = 0.35355339059327373f;
    const int posOff = (7 - iy)*15 + (7 - ix);

    __nv_bfloat16* op = aout + ((size_t)(bb*H + sy)*W + sx)*32;

    #pragma unroll 1
    for (int h = 0; h < 4; h++) {
        float lg[64];
        float mx = -1e30f;
        #pragma unroll
        for (int j = 0; j < 64; j++) {
            const int jy = j >> 3, jx = j & 7;
            float d = 0.f;
            #pragma unroll
            for (int dd = 0; dd < 8; dd++)
                d = fmaf(q[h*8 + dd], sK[j][h*8 + dd], d);
            float l = d*scale + sPos[jy*15 + jx + posOff];
            bool msk = (mR && ((iy >= 4) != (jy >= 4))) ||
                       (mC && ((ix >= 4) != (jx >= 4)));
            l = msk ? -1e30f : l;
            lg[j] = l;
            mx = fmaxf(mx, l);
        }
        float s = 0.f;
        #pragma unroll
        for (int j = 0; j < 64; j++) {
            float e = __expf(lg[j] - mx);
            lg[j] = e;
            s += e;
        }
        const float inv = 1.f / s;
        float oh[8];
        #pragma unroll
        for (int dd = 0; dd < 8; dd++) oh[dd] = 0.f;
        #pragma unroll
        for (int j = 0; j < 64; j++) {
            float p = lg[j];
            #pragma unroll
            for (int dd = 0; dd < 8; dd++)
                oh[dd] = fmaf(p, sV[j][h*8 + dd], oh[dd]);
        }
        #pragma unroll
        for (int dd = 0; dd < 8; dd += 2)
            *(__nv_bfloat162*)(op + h*8 + dd) =
                __floats2bfloat162_rn(oh[dd]*inv, oh[dd+1]*inv);
    }
}

// =====================================================================
// conv_out GEMM (32->3, 8 couts padded) + roll(+4,+4) + residual, fp32 out
// =====================================================================
__global__ __launch_bounds__(256, 2)
void convout_gemm_k(const __nv_bfloat16* __restrict__ in, const uint32_t* __restrict__ gB,
                    const float* __restrict__ bias, const float* __restrict__ xin,
                    float* __restrict__ out)
{
    extern __shared__ __align__(16) char sAb[];

    const int bb = blockIdx.z;
    const int x0 = blockIdx.x * 128;
    const int y0 = blockIdx.y * 2;
    const int tid = threadIdx.x;
    const int warp = tid >> 5, lane = tid & 31;
    const int warpRow = warp >> 2;
    const int pxBase  = (warp & 3) * 32;
    const int groupId = lane >> 2, quad = lane & 3;

    const uint32_t aLane = smem_u32(sAb) + (uint32_t)((lane & 15)*(PADB*2) + (lane >> 4)*16);

    const int co0 = quad*2, co1 = quad*2 + 1;
    float acc[2][4];
    {
        float b0 = co0 < 3 ? __ldg(&bias[co0]) : 0.f;
        float b1 = co1 < 3 ? __ldg(&bias[co1]) : 0.f;
        #pragma unroll
        for (int m = 0; m < 2; m++) {
            acc[m][0] = b0; acc[m][1] = b1;
            acc[m][2] = b0; acc[m][3] = b1;
        }
    }

    #pragma unroll
    for (int r = 0; r < 4; r++) {
        int y = y0 - 1 + r;
        bool yin = (unsigned)y < (unsigned)H;
        for (int i = tid; i < 130*4; i += 256) {
            int px = i >> 2, v = i & 3;
            int x = x0 - 1 + px;
            bool inb = yin && ((unsigned)x < (unsigned)W);
            const __nv_bfloat16* src = in +
                ((size_t)(bb*H + (inb ? y : 0))*W + (inb ? x : 0))*32 + v*8;
            cp16(smem_u32(sAb + (size_t)(r*130 + px)*(PADB*2) + v*16), src, inb ? 16 : 0);
        }
    }
    cp_commit_wait();
    __syncthreads();

    #pragma unroll
    for (int dy = 0; dy < 3; dy++) {
        #pragma unroll
        for (int dx = 0; dx < 3; dx++) {
            const uint32_t aBase = aLane +
                (uint32_t)(((warpRow + dy)*130 + pxBase + dx)*(PADB*2));
            const uint2* pb2 = (const uint2*)gB + (dy*3 + dx)*2*32 + lane;
            #pragma unroll
            for (int kk = 0; kk < 2; kk++) {
                uint2 L = __ldg(pb2 + kk*32);
                #pragma unroll
                for (int m = 0; m < 2; m++) {
                    uint32_t a0, a1, a2, a3;
                    ldmA(a0, a1, a2, a3, aBase + (uint32_t)(m*16*(PADB*2) + kk*32));
                    mma_bf16(acc[m][0], acc[m][1], acc[m][2], acc[m][3],
                             a0, a1, a2, a3, L.x, L.y);
                }
            }
        }
    }

    const int gy = y0 + warpRow;
    int oy = gy + 4; if (oy >= H) oy -= H;
    #pragma unroll
    for (int m = 0; m < 2; m++) {
        #pragma unroll
        for (int hh = 0; hh < 2; hh++) {
            int gx = x0 + pxBase + m*16 + groupId + hh*8;
            int ox = gx + 4; if (ox >= W) ox -= W;
            if (co0 < 3) {
                size_t idx = ((size_t)(bb*3 + co0)*H + oy)*W + ox;
                out[idx] = xin[idx] + acc[m][hh*2 + 0];
            }
            if (co1 < 3) {
                size_t idx = ((size_t)(bb*3 + co1)*H + oy)*W + ox;
                out[idx] = xin[idx] + acc[m][hh*2 + 1];
            }
        }
    }
}

// ---------------- launcher ----------------
extern "C" void kernel_launch(void* const* d_in, const int* in_sizes, int n_in,
                              void* d_out, int out_size)
{
    (void)in_sizes; (void)n_in; (void)out_size;
    const float* x   = (const float*)d_in[0];
    const float* wo  = (const float*)d_in[19];
    const float* bo  = (const float*)d_in[20];
    const float* pos = (const float*)d_in[21];
    float* out = (float*)d_out;

    __nv_bfloat16 *h1, *h2, *feat, *aout;
    uint32_t *bf1, *bf2, *bf3, *bfo;
    cudaGetSymbolAddress((void**)&h1,   g_h1);
    cudaGetSymbolAddress((void**)&h2,   g_h2);
    cudaGetSymbolAddress((void**)&feat, g_feat);
    cudaGetSymbolAddress((void**)&aout, g_aout);
    cudaGetSymbolAddress((void**)&bf1,  g_bf1);
    cudaGetSymbolAddress((void**)&bf2,  g_bf2);
    cudaGetSymbolAddress((void**)&bf3,  g_bf3);
    cudaGetSymbolAddress((void**)&bfo,  g_bfo);

    // B prep
    prep_b1_k<<<dim3(4, 3), 256>>>(
        (const float*)d_in[1], (const float*)d_in[7],  (const float*)d_in[13], bf1);
    prep_b2_k<2, 2, 64><<<dim3(36, 3), 256>>>(
        (const float*)d_in[3], (const float*)d_in[9],  (const float*)d_in[15], bf2);
    prep_b2_k<2, 1, 32><<<dim3(18, 3), 256>>>(
        (const float*)d_in[5], (const float*)d_in[11], (const float*)d_in[17], bf3);
    prep_bo_k<<<5, 256>>>(wo, bfo);

    dim3 g1(W/128, H/2, BATCH);     // conv1 fused: z = bb
    dim3 gg(W/128, H/2, BATCH*3);   // conv2/conv3: z = br*2 + bb

    conv1_im2col_k<<<g1, 256>>>(
        x, bf1,
        (const float*)d_in[2], (const float*)d_in[8], (const float*)d_in[14], h1);
    gemm_bf16_k<2, 2, 64, 32, true,  false><<<gg, 256, SMB>>>(
        h1, bf2,
        (const float*)d_in[4], (const float*)d_in[10], (const float*)d_in[16],
        h2, H1SZ, H2SZ);
    gemm_bf16_k<2, 1, 32, 96, false, true ><<<gg, 256, SMB>>>(
        h2, bf3,
        (const float*)d_in[6], (const float*)d_in[12], (const float*)d_in[18],
        feat, H2SZ, 0);

    attn_k<<<dim3(NWIN*NWIN, BATCH), 64>>>(feat, pos, aout);
    convout_gemm_k<<<g1, 256, SMB>>>(aout, bfo, bo, x, out);
}

// round 12
// speedup vs baseline: 2.1833x; 1.0419x over previous
#include <cuda_runtime.h>
#include <cuda_bf16.h>
#include <cstdint>
#include <cstddef>

#define H 384
#define W 384
#define BATCH 2
#define NWIN 48

#define H1SZ ((size_t)BATCH*H*W*64)   // elements per branch (bf16)
#define H2SZ ((size_t)BATCH*H*W*32)

// ---------------- scratch ----------------
__device__ __nv_bfloat16 g_h1[3*H1SZ];
__device__ __nv_bfloat16 g_h2[3*H2SZ];
__device__ __nv_bfloat16 g_feat[(size_t)BATCH*H*W*96];
__device__ __nv_bfloat16 g_aout[(size_t)BATCH*H*W*32];   // channel-last, shifted space
__device__ uint32_t g_bf1[3*1024];     // conv1 B frags (bf16x2, im2col K=32)
__device__ uint32_t g_bf2[3*9216];     // conv2 B frags
__device__ uint32_t g_bf3[3*4608];     // conv3 B frags
__device__ uint32_t g_bfo[1152];       // conv_out B frags (8 couts, 3 real)

// ---------------- helpers ----------------
__device__ __forceinline__ void mma_bf16(float& c0, float& c1, float& c2, float& c3,
                                         uint32_t a0, uint32_t a1, uint32_t a2, uint32_t a3,
                                         uint32_t b0, uint32_t b1) {
    asm volatile("mma.sync.aligned.m16n8k16.row.col.f32.bf16.bf16.f32 "
                 "{%0,%1,%2,%3}, {%4,%5,%6,%7}, {%8,%9}, {%0,%1,%2,%3};"
                 : "+f"(c0), "+f"(c1), "+f"(c2), "+f"(c3)
                 : "r"(a0), "r"(a1), "r"(a2), "r"(a3), "r"(b0), "r"(b1));
}
__device__ __forceinline__ void ldmA(uint32_t& r0, uint32_t& r1, uint32_t& r2, uint32_t& r3,
                                     uint32_t addr) {
    asm volatile("ldmatrix.sync.aligned.m8n8.x4.shared.b16 {%0,%1,%2,%3}, [%4];"
                 : "=r"(r0), "=r"(r1), "=r"(r2), "=r"(r3) : "r"(addr));
}
__device__ __forceinline__ uint32_t smem_u32(const void* p) {
    return (uint32_t)__cvta_generic_to_shared(p);
}
__device__ __forceinline__ void cp16(uint32_t dst, const void* src, int sz) {
    asm volatile("cp.async.cg.shared.global [%0], [%1], 16, %2;"
                 :: "r"(dst), "l"(src), "r"(sz));
}
__device__ __forceinline__ void cp4(uint32_t dst, const void* src, int sz) {
    asm volatile("cp.async.ca.shared.global [%0], [%1], 4, %2;"
                 :: "r"(dst), "l"(src), "r"(sz));
}
__device__ __forceinline__ void cp_commit_wait() {
    asm volatile("cp.async.commit_group;");
    asm volatile("cp.async.wait_group 0;");
}
// packed fp32x2
__device__ __forceinline__ unsigned long long pack2(float lo, float hi) {
    unsigned long long r;
    asm("mov.b64 %0, {%1, %2};" : "=l"(r) : "f"(lo), "f"(hi));
    return r;
}
__device__ __forceinline__ unsigned long long fma2(unsigned long long a,
                                                   unsigned long long b,
                                                   unsigned long long c) {
    unsigned long long d;
    asm("fma.rn.f32x2 %0, %1, %2, %3;" : "=l"(d) : "l"(a), "l"(b), "l"(c));
    return d;
}
__device__ __forceinline__ float lo2(unsigned long long v) {
    return __uint_as_float((unsigned)(v & 0xffffffffULL));
}
__device__ __forceinline__ float hi2(unsigned long long v) {
    return __uint_as_float((unsigned)(v >> 32));
}

// =====================================================================
// merged B prep: bf1 (3x1024) | bf2 (3x9216) | bf3 (3x4608) | bfo (1152)
// =====================================================================
__global__ void prep_all_k(const float* __restrict__ w1a, const float* __restrict__ w1b,
                           const float* __restrict__ w1c,
                           const float* __restrict__ w2a, const float* __restrict__ w2b,
                           const float* __restrict__ w2c,
                           const float* __restrict__ w3a, const float* __restrict__ w3b,
                           const float* __restrict__ w3c,
                           const float* __restrict__ wo,
                           uint32_t* __restrict__ bf1, uint32_t* __restrict__ bf2,
                           uint32_t* __restrict__ bf3, uint32_t* __restrict__ bfo)
{
    int gid = blockIdx.x*256 + threadIdx.x;

    if (gid < 3072) {                                   // conv1: im2col K=32 (27 real)
        int br = gid / 1024, idx = gid - br*1024;
        const float* wt = br == 0 ? w1a : (br == 1 ? w1b : w1c);
        int r    = idx & 3;
        int lane = (idx >> 2) & 31;
        int half = (idx >> 7) & 3;
        int kk   = idx >> 9;
        int n    = half*2 + (r >> 1);
        int breg = r & 1;
        int k0 = kk*16 + (lane & 3)*2 + breg*8;
        int co = n*8 + (lane >> 2);
        float v0 = 0.f, v1 = 0.f;
        if (k0 + 0 < 27) v0 = wt[(co*3 + (k0+0)/9)*9 + (k0+0)%9];
        if (k0 + 1 < 27) v1 = wt[(co*3 + (k0+1)/9)*9 + (k0+1)%9];
        __nv_bfloat162 pk = __floats2bfloat162_rn(v0, v1);
        bf1[gid] = *(uint32_t*)&pk;
        return;
    }
    gid -= 3072;
    if (gid < 27648) {                                  // conv2: CIN=64
        int br = gid / 9216, idx = gid - br*9216;
        const float* wt = br == 0 ? w2a : (br == 1 ? w2b : w2c);
        int r    = idx & 3;
        int lane = (idx >> 2) & 31;
        int half = (idx >> 7) & 1;
        int rest = idx >> 8;
        int kk   = rest & 1;
        int rest2 = rest >> 1;
        int dydx = rest2 % 9;
        int ch   = rest2 / 9;
        int n    = half*2 + (r >> 1);
        int breg = r & 1;
        int ci = ch*32 + kk*16 + (lane & 3)*2 + breg*8;
        int co = n*8 + (lane >> 2);
        __nv_bfloat162 pk = __floats2bfloat162_rn(
            wt[(co*64 + ci + 0)*9 + dydx], wt[(co*64 + ci + 1)*9 + dydx]);
        bf2[br*9216 + idx] = *(uint32_t*)&pk;
        return;
    }
    gid -= 27648;
    if (gid < 13824) {                                  // conv3: CIN=32
        int br = gid / 4608, idx = gid - br*4608;
        const float* wt = br == 0 ? w3a : (br == 1 ? w3b : w3c);
        int r    = idx & 3;
        int lane = (idx >> 2) & 31;
        int half = (idx >> 7) & 1;
        int rest = idx >> 8;
        int kk   = rest & 1;
        int dydx = rest >> 1;
        int n    = half*2 + (r >> 1);
        int breg = r & 1;
        int ci = kk*16 + (lane & 3)*2 + breg*8;
        int co = n*8 + (lane >> 2);
        __nv_bfloat162 pk = __floats2bfloat162_rn(
            wt[(co*32 + ci + 0)*9 + dydx], wt[(co*32 + ci + 1)*9 + dydx]);
        bf3[br*4608 + idx] = *(uint32_t*)&pk;
        return;
    }
    gid -= 13824;
    if (gid < 1152) {                                   // conv_out: 8 couts (3 real)
        int idx = gid;
        int breg = idx & 1;
        int lane = (idx >> 1) & 31;
        int kk   = (idx >> 6) & 1;
        int dydx = idx >> 7;
        int ci = kk*16 + (lane & 3)*2 + breg*8;
        int co = lane >> 2;
        float v0 = 0.f, v1 = 0.f;
        if (co < 3) {
            v0 = wo[(co*32 + ci + 0)*9 + dydx];
            v1 = wo[(co*32 + ci + 1)*9 + dydx];
        }
        __nv_bfloat162 pk = __floats2bfloat162_rn(v0, v1);
        bfo[idx] = *(uint32_t*)&pk;
    }
}

// =====================================================================
// conv1 fused: 3->64 x 3 branches. One fill + one im2col, 3 mainloops.
// =====================================================================
#define PADB 40

__global__ __launch_bounds__(256, 2)
void conv1_im2col_k(const float* __restrict__ in, const uint32_t* __restrict__ gB,
                    const float* __restrict__ bias0, const float* __restrict__ bias1,
                    const float* __restrict__ bias2, __nv_bfloat16* __restrict__ out)
{
    __shared__ float sRaw[3][4][132];
    __shared__ __align__(16) __nv_bfloat16 sA[256][PADB];

    const int bb = blockIdx.z;
    const int x0 = blockIdx.x * 128;
    const int y0 = blockIdx.y * 2;
    const int tid = threadIdx.x;
    const int warp = tid >> 5, lane = tid & 31;
    const int warpRow = warp >> 2;
    const int pxBase  = (warp & 3) * 32;
    const int groupId = lane >> 2, quad = lane & 3;

    for (int i = tid; i < 3*4*130; i += 256) {
        int ci = i / 520;
        int r2 = i - ci*520;
        int rr = r2 / 130;
        int xx = r2 - rr*130;
        int y = y0 - 1 + rr, x = x0 - 1 + xx;
        bool inb = ((unsigned)y < (unsigned)H) && ((unsigned)x < (unsigned)W);
        const float* src = in + ((size_t)(bb*3 + ci)*H + (inb ? y : 0))*W + (inb ? x : 0);
        cp4(smem_u32(&sRaw[ci][rr][xx]), src, inb ? 4 : 0);
    }
    cp_commit_wait();
    __syncthreads();

    {
        int r = tid >> 7, px = tid & 127;
        float vals[32];
        #pragma unroll
        for (int ci = 0; ci < 3; ci++)
            #pragma unroll
            for (int dy = 0; dy < 3; dy++)
                #pragma unroll
                for (int dx = 0; dx < 3; dx++)
                    vals[ci*9 + dy*3 + dx] = sRaw[ci][r + dy][px + dx];
        #pragma unroll
        for (int k = 27; k < 32; k++) vals[k] = 0.f;
        uint32_t pk[16];
        #pragma unroll
        for (int t = 0; t < 16; t++) {
            __nv_bfloat162 p = __floats2bfloat162_rn(vals[2*t], vals[2*t+1]);
            pk[t] = *(uint32_t*)&p;
        }
        uint4* dstp = (uint4*)&sA[tid][0];
        dstp[0] = make_uint4(pk[0],  pk[1],  pk[2],  pk[3]);
        dstp[1] = make_uint4(pk[4],  pk[5],  pk[6],  pk[7]);
        dstp[2] = make_uint4(pk[8],  pk[9],  pk[10], pk[11]);
        dstp[3] = make_uint4(pk[12], pk[13], pk[14], pk[15]);
    }
    __syncthreads();

    const uint32_t aLane = smem_u32(sA) +
        (uint32_t)((warpRow*128 + pxBase + (lane & 15))*(PADB*2) + (lane >> 4)*16);
    const int yOut = y0 + warpRow;

    #pragma unroll 1
    for (int br = 0; br < 3; br++) {
        const float* bias = br == 0 ? bias0 : (br == 1 ? bias1 : bias2);
        const uint4* pb4 = (const uint4*)(gB + br*1024) + lane;
        __nv_bfloat16* outp = out + (size_t)br * H1SZ;

        float acc[2][8][4];
        #pragma unroll
        for (int n = 0; n < 8; n++) {
            float b0 = __ldg(&bias[n*8 + quad*2 + 0]);
            float b1 = __ldg(&bias[n*8 + quad*2 + 1]);
            #pragma unroll
            for (int m = 0; m < 2; m++) {
                acc[m][n][0] = b0; acc[m][n][1] = b1;
                acc[m][n][2] = b0; acc[m][n][3] = b1;
            }
        }

        #pragma unroll
        for (int kk = 0; kk < 2; kk++) {
            uint4 L0 = __ldg(pb4 + kk*128);
            uint4 L1 = __ldg(pb4 + kk*128 + 32);
            uint4 L2 = __ldg(pb4 + kk*128 + 64);
            uint4 L3 = __ldg(pb4 + kk*128 + 96);
            #pragma unroll
            for (int m = 0; m < 2; m++) {
                uint32_t a0, a1, a2, a3;
                ldmA(a0, a1, a2, a3, aLane + (uint32_t)(m*16*(PADB*2) + kk*32));
                mma_bf16(acc[m][0][0], acc[m][0][1], acc[m][0][2], acc[m][0][3], a0,a1,a2,a3, L0.x, L0.y);
                mma_bf16(acc[m][1][0], acc[m][1][1], acc[m][1][2], acc[m][1][3], a0,a1,a2,a3, L0.z, L0.w);
                mma_bf16(acc[m][2][0], acc[m][2][1], acc[m][2][2], acc[m][2][3], a0,a1,a2,a3, L1.x, L1.y);
                mma_bf16(acc[m][3][0], acc[m][3][1], acc[m][3][2], acc[m][3][3], a0,a1,a2,a3, L1.z, L1.w);
                mma_bf16(acc[m][4][0], acc[m][4][1], acc[m][4][2], acc[m][4][3], a0,a1,a2,a3, L2.x, L2.y);
                mma_bf16(acc[m][5][0], acc[m][5][1], acc[m][5][2], acc[m][5][3], a0,a1,a2,a3, L2.z, L2.w);
                mma_bf16(acc[m][6][0], acc[m][6][1], acc[m][6][2], acc[m][6][3], a0,a1,a2,a3, L3.x, L3.y);
                mma_bf16(acc[m][7][0], acc[m][7][1], acc[m][7][2], acc[m][7][3], a0,a1,a2,a3, L3.z, L3.w);
            }
        }

        #pragma unroll
        for (int m = 0; m < 2; m++) {
            #pragma unroll
            for (int hh = 0; hh < 2; hh++) {
                int px = pxBase + m*16 + groupId + hh*8;
                __nv_bfloat16* op = outp + ((size_t)(bb*H + yOut)*W + x0 + px)*64 + quad*2;
                #pragma unroll
                for (int n = 0; n < 8; n++) {
                    float v0 = fmaxf(acc[m][n][hh*2 + 0], 0.f);
                    float v1 = fmaxf(acc[m][n][hh*2 + 1], 0.f);
                    *(__nv_bfloat162*)(op + n*8) = __floats2bfloat162_rn(v0, v1);
                }
            }
        }
    }
}

// =====================================================================
// bf16 implicit-GEMM conv (conv2/conv3), cp.async fills.
// =====================================================================
#define SMB (4*130*PADB*2)

template<int KSTEPS, int NCHUNK, int CINTOT, int OSTR, bool RELU, bool FEAT>
__global__ __launch_bounds__(256, 2)
void gemm_bf16_k(const __nv_bfloat16* __restrict__ in, const uint32_t* __restrict__ gB,
                 const float* __restrict__ bias0, const float* __restrict__ bias1,
                 const float* __restrict__ bias2, __nv_bfloat16* __restrict__ out,
                 size_t inStride, size_t outStride)
{
    extern __shared__ __align__(16) char sAb[];
    constexpr int BSZ = NCHUNK*9*KSTEPS*256;

    const int z  = blockIdx.z;
    const int bb = z & 1;
    const int br = z >> 1;
    const float* bias = br == 0 ? bias0 : (br == 1 ? bias1 : bias2);
    in  += (size_t)br * inStride;
    out += (size_t)br * outStride;
    gB  += br * BSZ;
    const int outOff = FEAT ? br*32 : 0;

    const int x0 = blockIdx.x * 128;
    const int y0 = blockIdx.y * 2;
    const int tid = threadIdx.x;
    const int warp = tid >> 5, lane = tid & 31;
    const int warpRow = warp >> 2;
    const int pxBase  = (warp & 3) * 32;
    const int groupId = lane >> 2, quad = lane & 3;

    const uint32_t aLane = smem_u32(sAb) + (uint32_t)((lane & 15)*(PADB*2) + (lane >> 4)*16);

    float acc[2][4][4];
    #pragma unroll
    for (int n = 0; n < 4; n++) {
        float b0 = __ldg(&bias[n*8 + quad*2 + 0]);
        float b1 = __ldg(&bias[n*8 + quad*2 + 1]);
        #pragma unroll
        for (int m = 0; m < 2; m++) {
            acc[m][n][0] = b0; acc[m][n][1] = b1;
            acc[m][n][2] = b0; acc[m][n][3] = b1;
        }
    }

    #pragma unroll 1
    for (int ch = 0; ch < NCHUNK; ch++) {
        __syncthreads();
        #pragma unroll
        for (int r = 0; r < 4; r++) {
            int y = y0 - 1 + r;
            bool yin = (unsigned)y < (unsigned)H;
            for (int i = tid; i < 130*4; i += 256) {
                int px = i >> 2, v = i & 3;
                int x = x0 - 1 + px;
                bool inb = yin && ((unsigned)x < (unsigned)W);
                const __nv_bfloat16* src = in +
                    ((size_t)(bb*H + (inb ? y : 0))*W + (inb ? x : 0))*CINTOT + ch*32 + v*8;
                cp16(smem_u32(sAb + (size_t)(r*130 + px)*(PADB*2) + v*16), src, inb ? 16 : 0);
            }
        }
        cp_commit_wait();
        __syncthreads();

        #pragma unroll
        for (int dy = 0; dy < 3; dy++) {
            #pragma unroll
            for (int dx = 0; dx < 3; dx++) {
                const uint32_t aBase = aLane +
                    (uint32_t)(((warpRow + dy)*130 + pxBase + dx)*(PADB*2));
                const uint4* pb4 = (const uint4*)gB + ((ch*9 + dy*3 + dx)*KSTEPS)*64 + lane;
                #pragma unroll
                for (int kk = 0; kk < KSTEPS; kk++) {
                    uint4 L0 = __ldg(pb4 + kk*64);
                    uint4 L1 = __ldg(pb4 + kk*64 + 32);
                    #pragma unroll
                    for (int m = 0; m < 2; m++) {
                        uint32_t a0, a1, a2, a3;
                        ldmA(a0, a1, a2, a3, aBase + (uint32_t)(m*16*(PADB*2) + kk*32));
                        mma_bf16(acc[m][0][0], acc[m][0][1], acc[m][0][2], acc[m][0][3],
                                 a0, a1, a2, a3, L0.x, L0.y);
                        mma_bf16(acc[m][1][0], acc[m][1][1], acc[m][1][2], acc[m][1][3],
                                 a0, a1, a2, a3, L0.z, L0.w);
                        mma_bf16(acc[m][2][0], acc[m][2][1], acc[m][2][2], acc[m][2][3],
                                 a0, a1, a2, a3, L1.x, L1.y);
                        mma_bf16(acc[m][3][0], acc[m][3][1], acc[m][3][2], acc[m][3][3],
                                 a0, a1, a2, a3, L1.z, L1.w);
                    }
                }
            }
        }
    }

    const int yOut = y0 + warpRow;
    #pragma unroll
    for (int m = 0; m < 2; m++) {
        #pragma unroll
        for (int hh = 0; hh < 2; hh++) {
            int px = pxBase + m*16 + groupId + hh*8;
            __nv_bfloat16* op = out + ((size_t)(bb*H + yOut)*W + x0 + px)*OSTR + outOff + quad*2;
            #pragma unroll
            for (int n = 0; n < 4; n++) {
                float v0 = acc[m][n][hh*2 + 0];
                float v1 = acc[m][n][hh*2 + 1];
                if (RELU) { v0 = fmaxf(v0, 0.f); v1 = fmaxf(v1, 0.f); }
                *(__nv_bfloat162*)(op + n*8) = __floats2bfloat162_rn(v0, v1);
            }
        }
    }
}

// =====================================================================
// shifted-window attention: 2 windows/block (128 thr), f32x2 packed math
// =====================================================================
__global__ __launch_bounds__(128)
void attn_k(const __nv_bfloat16* __restrict__ feat, const float* __restrict__ pos,
            __nv_bfloat16* __restrict__ aout)
{
    __shared__ float sK[2][64][32];
    __shared__ float sV[2][64][32];
    __shared__ float sPos[225];

    const int bb = blockIdx.y;
    const int tid = threadIdx.x;
    const int sub = tid >> 6;           // which window half
    const int t64 = tid & 63;
    const int w   = blockIdx.x*2 + sub;
    const int wh = w / NWIN, ww = w - wh*NWIN;
    const int iy = t64 >> 3, ix = t64 & 7;
    const int sy = wh*8 + iy, sx = ww*8 + ix;
    int y = sy + 4; if (y >= H) y -= H;
    int x = sx + 4; if (x >= W) x -= W;

    // fill own window's K/V (64 tokens x 32 ch each)
    for (int idx = t64; idx < 64*4; idx += 64) {
        int j = idx >> 2, part = idx & 3;
        int jy = j >> 3, jx = j & 7;
        int yy = wh*8 + jy + 4; if (yy >= H) yy -= H;
        int xx = ww*8 + jx + 4; if (xx >= W) xx -= W;
        const __nv_bfloat16* p = feat + ((size_t)(bb*H + yy)*W + xx)*96;
        uint4 uk = *(const uint4*)(p + 32 + part*8);
        uint4 uv = *(const uint4*)(p + 64 + part*8);
        const __nv_bfloat162* hk = (const __nv_bfloat162*)&uk;
        const __nv_bfloat162* hv = (const __nv_bfloat162*)&uv;
        #pragma unroll
        for (int t = 0; t < 4; t++) {
            float2 fk = __bfloat1622float2(hk[t]);
            float2 fv = __bfloat1622float2(hv[t]);
            sK[sub][j][part*8 + t*2 + 0] = fk.x;
            sK[sub][j][part*8 + t*2 + 1] = fk.y;
            sV[sub][j][part*8 + t*2 + 0] = fv.x;
            sV[sub][j][part*8 + t*2 + 1] = fv.y;
        }
    }
    for (int idx = tid; idx < 225; idx += 128) sPos[idx] = pos[idx];

    // q as 16 packed pairs
    unsigned long long q2[16];
    {
        const __nv_bfloat16* fp = feat + ((size_t)(bb*H + y)*W + x)*96;
        #pragma unroll
        for (int part = 0; part < 4; part++) {
            uint4 u = *(const uint4*)(fp + part*8);
            const __nv_bfloat162* hq = (const __nv_bfloat162*)&u;
            #pragma unroll
            for (int t = 0; t < 4; t++) {
                float2 f = __bfloat1622float2(hq[t]);
                q2[part*4 + t] = pack2(f.x, f.y);
            }
        }
    }
    __syncthreads();

    const bool mR = (wh == NWIN-1);
    const bool mC = (ww == NWIN-1);
    const float scale = 0.35355339059327373f;
    const int posOff = (7 - iy)*15 + (7 - ix);

    __nv_bfloat16* op = aout + ((size_t)(bb*H + sy)*W + sx)*32;

    #pragma unroll 1
    for (int h = 0; h < 4; h++) {
        float lg[64];
        float mx = -1e30f;
        #pragma unroll
        for (int j = 0; j < 64; j++) {
            const int jy = j >> 3, jx = j & 7;
            const unsigned long long* kp = (const unsigned long long*)&sK[sub][j][h*8];
            unsigned long long d2 = fma2(q2[h*4+0], kp[0], 0ULL);
            d2 = fma2(q2[h*4+1], kp[1], d2);
            d2 = fma2(q2[h*4+2], kp[2], d2);
            d2 = fma2(q2[h*4+3], kp[3], d2);
            float l = (lo2(d2) + hi2(d2))*scale + sPos[jy*15 + jx + posOff];
            bool msk = (mR && ((iy >= 4) != (jy >= 4))) ||
                       (mC && ((ix >= 4) != (jx >= 4)));
            l = msk ? -1e30f : l;
            lg[j] = l;
            mx = fmaxf(mx, l);
        }
        float s = 0.f;
        #pragma unroll
        for (int j = 0; j < 64; j++) {
            float e = __expf(lg[j] - mx);
            lg[j] = e;
            s += e;
        }
        const float inv = 1.f / s;
        unsigned long long oh2[4];
        #pragma unroll
        for (int d = 0; d < 4; d++) oh2[d] = 0ULL;
        #pragma unroll
        for (int j = 0; j < 64; j++) {
            unsigned long long pp = pack2(lg[j], lg[j]);
            const unsigned long long* vp = (const unsigned long long*)&sV[sub][j][h*8];
            oh2[0] = fma2(pp, vp[0], oh2[0]);
            oh2[1] = fma2(pp, vp[1], oh2[1]);
            oh2[2] = fma2(pp, vp[2], oh2[2]);
            oh2[3] = fma2(pp, vp[3], oh2[3]);
        }
        #pragma unroll
        for (int d = 0; d < 4; d++)
            *(__nv_bfloat162*)(op + h*8 + d*2) =
                __floats2bfloat162_rn(lo2(oh2[d])*inv, hi2(oh2[d])*inv);
    }
}

// =====================================================================
// conv_out GEMM (32->3, 8 couts padded) + roll(+4,+4) + residual, fp32 out
// =====================================================================
__global__ __launch_bounds__(256, 2)
void convout_gemm_k(const __nv_bfloat16* __restrict__ in, const uint32_t* __restrict__ gB,
                    const float* __restrict__ bias, const float* __restrict__ xin,
                    float* __restrict__ out)
{
    extern __shared__ __align__(16) char sAb[];

    const int bb = blockIdx.z;
    const int x0 = blockIdx.x * 128;
    const int y0 = blockIdx.y * 2;
    const int tid = threadIdx.x;
    const int warp = tid >> 5, lane = tid & 31;
    const int warpRow = warp >> 2;
    const int pxBase  = (warp & 3) * 32;
    const int groupId = lane >> 2, quad = lane & 3;

    const uint32_t aLane = smem_u32(sAb) + (uint32_t)((lane & 15)*(PADB*2) + (lane >> 4)*16);

    const int co0 = quad*2, co1 = quad*2 + 1;
    float acc[2][4];
    {
        float b0 = co0 < 3 ? __ldg(&bias[co0]) : 0.f;
        float b1 = co1 < 3 ? __ldg(&bias[co1]) : 0.f;
        #pragma unroll
        for (int m = 0; m < 2; m++) {
            acc[m][0] = b0; acc[m][1] = b1;
            acc[m][2] = b0; acc[m][3] = b1;
        }
    }

    #pragma unroll
    for (int r = 0; r < 4; r++) {
        int y = y0 - 1 + r;
        bool yin = (unsigned)y < (unsigned)H;
        for (int i = tid; i < 130*4; i += 256) {
            int px = i >> 2, v = i & 3;
            int x = x0 - 1 + px;
            bool inb = yin && ((unsigned)x < (unsigned)W);
            const __nv_bfloat16* src = in +
                ((size_t)(bb*H + (inb ? y : 0))*W + (inb ? x : 0))*32 + v*8;
            cp16(smem_u32(sAb + (size_t)(r*130 + px)*(PADB*2) + v*16), src, inb ? 16 : 0);
        }
    }
    cp_commit_wait();
    __syncthreads();

    #pragma unroll
    for (int dy = 0; dy < 3; dy++) {
        #pragma unroll
        for (int dx = 0; dx < 3; dx++) {
            const uint32_t aBase = aLane +
                (uint32_t)(((warpRow + dy)*130 + pxBase + dx)*(PADB*2));
            const uint2* pb2 = (const uint2*)gB + (dy*3 + dx)*2*32 + lane;
            #pragma unroll
            for (int kk = 0; kk < 2; kk++) {
                uint2 L = __ldg(pb2 + kk*32);
                #pragma unroll
                for (int m = 0; m < 2; m++) {
                    uint32_t a0, a1, a2, a3;
                    ldmA(a0, a1, a2, a3, aBase + (uint32_t)(m*16*(PADB*2) + kk*32));
                    mma_bf16(acc[m][0], acc[m][1], acc[m][2], acc[m][3],
                             a0, a1, a2, a3, L.x, L.y);
                }
            }
        }
    }

    const int gy = y0 + warpRow;
    int oy = gy + 4; if (oy >= H) oy -= H;
    #pragma unroll
    for (int m = 0; m < 2; m++) {
        #pragma unroll
        for (int hh = 0; hh < 2; hh++) {
            int gx = x0 + pxBase + m*16 + groupId + hh*8;
            int ox = gx + 4; if (ox >= W) ox -= W;
            if (co0 < 3) {
                size_t idx = ((size_t)(bb*3 + co0)*H + oy)*W + ox;
                out[idx] = xin[idx] + acc[m][hh*2 + 0];
            }
            if (co1 < 3) {
                size_t idx = ((size_t)(bb*3 + co1)*H + oy)*W + ox;
                out[idx] = xin[idx] + acc[m][hh*2 + 1];
            }
        }
    }
}

// ---------------- launcher ----------------
extern "C" void kernel_launch(void* const* d_in, const int* in_sizes, int n_in,
                              void* d_out, int out_size)
{
    (void)in_sizes; (void)n_in; (void)out_size;
    const float* x   = (const float*)d_in[0];
    const float* wo  = (const float*)d_in[19];
    const float* bo  = (const float*)d_in[20];
    const float* pos = (const float*)d_in[21];
    float* out = (float*)d_out;

    __nv_bfloat16 *h1, *h2, *feat, *aout;
    uint32_t *bf1, *bf2, *bf3, *bfo;
    cudaGetSymbolAddress((void**)&h1,   g_h1);
    cudaGetSymbolAddress((void**)&h2,   g_h2);
    cudaGetSymbolAddress((void**)&feat, g_feat);
    cudaGetSymbolAddress((void**)&aout, g_aout);
    cudaGetSymbolAddress((void**)&bf1,  g_bf1);
    cudaGetSymbolAddress((void**)&bf2,  g_bf2);
    cudaGetSymbolAddress((void**)&bf3,  g_bf3);
    cudaGetSymbolAddress((void**)&bfo,  g_bfo);

    // single merged B prep (45696 elements)
    prep_all_k<<<179, 256>>>(
        (const float*)d_in[1], (const float*)d_in[7],  (const float*)d_in[13],
        (const float*)d_in[3], (const float*)d_in[9],  (const float*)d_in[15],
        (const float*)d_in[5], (const float*)d_in[11], (const float*)d_in[17],
        wo, bf1, bf2, bf3, bfo);

    dim3 g1(W/128, H/2, BATCH);     // conv1 fused: z = bb
    dim3 gg(W/128, H/2, BATCH*3);   // conv2/conv3: z = br*2 + bb

    conv1_im2col_k<<<g1, 256>>>(
        x, bf1,
        (const float*)d_in[2], (const float*)d_in[8], (const float*)d_in[14], h1);
    gemm_bf16_k<2, 2, 64, 32, true,  false><<<gg, 256, SMB>>>(
        h1, bf2,
        (const float*)d_in[4], (const float*)d_in[10], (const float*)d_in[16],
        h2, H1SZ, H2SZ);
    gemm_bf16_k<2, 1, 32, 96, false, true ><<<gg, 256, SMB>>>(
        h2, bf3,
        (const float*)d_in[6], (const float*)d_in[12], (const float*)d_in[18],
        feat, H2SZ, 0);

    attn_k<<<dim3(NWIN*NWIN/2, BATCH), 128>>>(feat, pos, aout);
    convout_gemm_k<<<g1, 256, SMB>>>(aout, bfo, bo, x, out);
}

// round 13
// speedup vs baseline: 2.1969x; 1.0062x over previous
#include <cuda_runtime.h>
#include <cuda_bf16.h>
#include <cstdint>
#include <cstddef>

#define H 384
#define W 384
#define BATCH 2
#define NWIN 48

#define H1SZ ((size_t)BATCH*H*W*64)   // elements per branch (bf16)
#define H2SZ ((size_t)BATCH*H*W*32)

// ---------------- scratch ----------------
__device__ __nv_bfloat16 g_h1[3*H1SZ];
__device__ __nv_bfloat16 g_h2[3*H2SZ];
__device__ __nv_bfloat16 g_feat[(size_t)BATCH*H*W*96];
__device__ __nv_bfloat16 g_aout[(size_t)BATCH*H*W*32];   // channel-last, shifted space
__device__ uint32_t g_bf1[3*1024];     // conv1 B frags (bf16x2, im2col K=32)
__device__ uint32_t g_bf2[3*9216];     // conv2 B frags
__device__ uint32_t g_bf3[3*4608];     // conv3 B frags
__device__ uint32_t g_bfo[1152];       // conv_out B frags (8 couts, 3 real)

// ---------------- helpers ----------------
__device__ __forceinline__ void mma_bf16(float& c0, float& c1, float& c2, float& c3,
                                         uint32_t a0, uint32_t a1, uint32_t a2, uint32_t a3,
                                         uint32_t b0, uint32_t b1) {
    asm volatile("mma.sync.aligned.m16n8k16.row.col.f32.bf16.bf16.f32 "
                 "{%0,%1,%2,%3}, {%4,%5,%6,%7}, {%8,%9}, {%0,%1,%2,%3};"
                 : "+f"(c0), "+f"(c1), "+f"(c2), "+f"(c3)
                 : "r"(a0), "r"(a1), "r"(a2), "r"(a3), "r"(b0), "r"(b1));
}
__device__ __forceinline__ void ldmA(uint32_t& r0, uint32_t& r1, uint32_t& r2, uint32_t& r3,
                                     uint32_t addr) {
    asm volatile("ldmatrix.sync.aligned.m8n8.x4.shared.b16 {%0,%1,%2,%3}, [%4];"
                 : "=r"(r0), "=r"(r1), "=r"(r2), "=r"(r3) : "r"(addr));
}
__device__ __forceinline__ uint32_t smem_u32(const void* p) {
    return (uint32_t)__cvta_generic_to_shared(p);
}
__device__ __forceinline__ void cp16(uint32_t dst, const void* src, int sz) {
    asm volatile("cp.async.cg.shared.global [%0], [%1], 16, %2;"
                 :: "r"(dst), "l"(src), "r"(sz));
}
__device__ __forceinline__ void cp4(uint32_t dst, const void* src, int sz) {
    asm volatile("cp.async.ca.shared.global [%0], [%1], 4, %2;"
                 :: "r"(dst), "l"(src), "r"(sz));
}
__device__ __forceinline__ void cp_commit_wait() {
    asm volatile("cp.async.commit_group;");
    asm volatile("cp.async.wait_group 0;");
}
// packed fp32x2
__device__ __forceinline__ unsigned long long pack2(float lo, float hi) {
    unsigned long long r;
    asm("mov.b64 %0, {%1, %2};" : "=l"(r) : "f"(lo), "f"(hi));
    return r;
}
__device__ __forceinline__ unsigned long long fma2(unsigned long long a,
                                                   unsigned long long b,
                                                   unsigned long long c) {
    unsigned long long d;
    asm("fma.rn.f32x2 %0, %1, %2, %3;" : "=l"(d) : "l"(a), "l"(b), "l"(c));
    return d;
}
__device__ __forceinline__ float lo2(unsigned long long v) {
    return __uint_as_float((unsigned)(v & 0xffffffffULL));
}
__device__ __forceinline__ float hi2(unsigned long long v) {
    return __uint_as_float((unsigned)(v >> 32));
}

// =====================================================================
// merged B prep: bf1 (3x1024) | bf2 (3x9216) | bf3 (3x4608) | bfo (1152)
// =====================================================================
__global__ void prep_all_k(const float* __restrict__ w1a, const float* __restrict__ w1b,
                           const float* __restrict__ w1c,
                           const float* __restrict__ w2a, const float* __restrict__ w2b,
                           const float* __restrict__ w2c,
                           const float* __restrict__ w3a, const float* __restrict__ w3b,
                           const float* __restrict__ w3c,
                           const float* __restrict__ wo,
                           uint32_t* __restrict__ bf1, uint32_t* __restrict__ bf2,
                           uint32_t* __restrict__ bf3, uint32_t* __restrict__ bfo)
{
    int gid = blockIdx.x*256 + threadIdx.x;

    if (gid < 3072) {                                   // conv1: im2col K=32 (27 real)
        int br = gid / 1024, idx = gid - br*1024;
        const float* wt = br == 0 ? w1a : (br == 1 ? w1b : w1c);
        int r    = idx & 3;
        int lane = (idx >> 2) & 31;
        int half = (idx >> 7) & 3;
        int kk   = idx >> 9;
        int n    = half*2 + (r >> 1);
        int breg = r & 1;
        int k0 = kk*16 + (lane & 3)*2 + breg*8;
        int co = n*8 + (lane >> 2);
        float v0 = 0.f, v1 = 0.f;
        if (k0 + 0 < 27) v0 = wt[(co*3 + (k0+0)/9)*9 + (k0+0)%9];
        if (k0 + 1 < 27) v1 = wt[(co*3 + (k0+1)/9)*9 + (k0+1)%9];
        __nv_bfloat162 pk = __floats2bfloat162_rn(v0, v1);
        bf1[gid] = *(uint32_t*)&pk;
        return;
    }
    gid -= 3072;
    if (gid < 27648) {                                  // conv2: CIN=64
        int br = gid / 9216, idx = gid - br*9216;
        const float* wt = br == 0 ? w2a : (br == 1 ? w2b : w2c);
        int r    = idx & 3;
        int lane = (idx >> 2) & 31;
        int half = (idx >> 7) & 1;
        int rest = idx >> 8;
        int kk   = rest & 1;
        int rest2 = rest >> 1;
        int dydx = rest2 % 9;
        int ch   = rest2 / 9;
        int n    = half*2 + (r >> 1);
        int breg = r & 1;
        int ci = ch*32 + kk*16 + (lane & 3)*2 + breg*8;
        int co = n*8 + (lane >> 2);
        __nv_bfloat162 pk = __floats2bfloat162_rn(
            wt[(co*64 + ci + 0)*9 + dydx], wt[(co*64 + ci + 1)*9 + dydx]);
        bf2[br*9216 + idx] = *(uint32_t*)&pk;
        return;
    }
    gid -= 27648;
    if (gid < 13824) {                                  // conv3: CIN=32
        int br = gid / 4608, idx = gid - br*4608;
        const float* wt = br == 0 ? w3a : (br == 1 ? w3b : w3c);
        int r    = idx & 3;
        int lane = (idx >> 2) & 31;
        int half = (idx >> 7) & 1;
        int rest = idx >> 8;
        int kk   = rest & 1;
        int dydx = rest >> 1;
        int n    = half*2 + (r >> 1);
        int breg = r & 1;
        int ci = kk*16 + (lane & 3)*2 + breg*8;
        int co = n*8 + (lane >> 2);
        __nv_bfloat162 pk = __floats2bfloat162_rn(
            wt[(co*32 + ci + 0)*9 + dydx], wt[(co*32 + ci + 1)*9 + dydx]);
        bf3[br*4608 + idx] = *(uint32_t*)&pk;
        return;
    }
    gid -= 13824;
    if (gid < 1152) {                                   // conv_out: 8 couts (3 real)
        int idx = gid;
        int breg = idx & 1;
        int lane = (idx >> 1) & 31;
        int kk   = (idx >> 6) & 1;
        int dydx = idx >> 7;
        int ci = kk*16 + (lane & 3)*2 + breg*8;
        int co = lane >> 2;
        float v0 = 0.f, v1 = 0.f;
        if (co < 3) {
            v0 = wo[(co*32 + ci + 0)*9 + dydx];
            v1 = wo[(co*32 + ci + 1)*9 + dydx];
        }
        __nv_bfloat162 pk = __floats2bfloat162_rn(v0, v1);
        bfo[idx] = *(uint32_t*)&pk;
    }
}

// =====================================================================
// conv1 fused: 3->64 x 3 branches. One fill + one im2col, 3 mainloops.
// =====================================================================
#define PADB 40

__global__ __launch_bounds__(256, 2)
void conv1_im2col_k(const float* __restrict__ in, const uint32_t* __restrict__ gB,
                    const float* __restrict__ bias0, const float* __restrict__ bias1,
                    const float* __restrict__ bias2, __nv_bfloat16* __restrict__ out)
{
    __shared__ float sRaw[3][4][132];
    __shared__ __align__(16) __nv_bfloat16 sA[256][PADB];

    const int bb = blockIdx.z;
    const int x0 = blockIdx.x * 128;
    const int y0 = blockIdx.y * 2;
    const int tid = threadIdx.x;
    const int warp = tid >> 5, lane = tid & 31;
    const int warpRow = warp >> 2;
    const int pxBase  = (warp & 3) * 32;
    const int groupId = lane >> 2, quad = lane & 3;

    for (int i = tid; i < 3*4*130; i += 256) {
        int ci = i / 520;
        int r2 = i - ci*520;
        int rr = r2 / 130;
        int xx = r2 - rr*130;
        int y = y0 - 1 + rr, x = x0 - 1 + xx;
        bool inb = ((unsigned)y < (unsigned)H) && ((unsigned)x < (unsigned)W);
        const float* src = in + ((size_t)(bb*3 + ci)*H + (inb ? y : 0))*W + (inb ? x : 0);
        cp4(smem_u32(&sRaw[ci][rr][xx]), src, inb ? 4 : 0);
    }
    cp_commit_wait();
    __syncthreads();

    {
        int r = tid >> 7, px = tid & 127;
        float vals[32];
        #pragma unroll
        for (int ci = 0; ci < 3; ci++)
            #pragma unroll
            for (int dy = 0; dy < 3; dy++)
                #pragma unroll
                for (int dx = 0; dx < 3; dx++)
                    vals[ci*9 + dy*3 + dx] = sRaw[ci][r + dy][px + dx];
        #pragma unroll
        for (int k = 27; k < 32; k++) vals[k] = 0.f;
        uint32_t pk[16];
        #pragma unroll
        for (int t = 0; t < 16; t++) {
            __nv_bfloat162 p = __floats2bfloat162_rn(vals[2*t], vals[2*t+1]);
            pk[t] = *(uint32_t*)&p;
        }
        uint4* dstp = (uint4*)&sA[tid][0];
        dstp[0] = make_uint4(pk[0],  pk[1],  pk[2],  pk[3]);
        dstp[1] = make_uint4(pk[4],  pk[5],  pk[6],  pk[7]);
        dstp[2] = make_uint4(pk[8],  pk[9],  pk[10], pk[11]);
        dstp[3] = make_uint4(pk[12], pk[13], pk[14], pk[15]);
    }
    __syncthreads();

    const uint32_t aLane = smem_u32(sA) +
        (uint32_t)((warpRow*128 + pxBase + (lane & 15))*(PADB*2) + (lane >> 4)*16);
    const int yOut = y0 + warpRow;

    #pragma unroll 1
    for (int br = 0; br < 3; br++) {
        const float* bias = br == 0 ? bias0 : (br == 1 ? bias1 : bias2);
        const uint4* pb4 = (const uint4*)(gB + br*1024) + lane;
        __nv_bfloat16* outp = out + (size_t)br * H1SZ;

        float acc[2][8][4];
        #pragma unroll
        for (int n = 0; n < 8; n++) {
            float b0 = __ldg(&bias[n*8 + quad*2 + 0]);
            float b1 = __ldg(&bias[n*8 + quad*2 + 1]);
            #pragma unroll
            for (int m = 0; m < 2; m++) {
                acc[m][n][0] = b0; acc[m][n][1] = b1;
                acc[m][n][2] = b0; acc[m][n][3] = b1;
            }
        }

        #pragma unroll
        for (int kk = 0; kk < 2; kk++) {
            uint4 L0 = __ldg(pb4 + kk*128);
            uint4 L1 = __ldg(pb4 + kk*128 + 32);
            uint4 L2 = __ldg(pb4 + kk*128 + 64);
            uint4 L3 = __ldg(pb4 + kk*128 + 96);
            #pragma unroll
            for (int m = 0; m < 2; m++) {
                uint32_t a0, a1, a2, a3;
                ldmA(a0, a1, a2, a3, aLane + (uint32_t)(m*16*(PADB*2) + kk*32));
                mma_bf16(acc[m][0][0], acc[m][0][1], acc[m][0][2], acc[m][0][3], a0,a1,a2,a3, L0.x, L0.y);
                mma_bf16(acc[m][1][0], acc[m][1][1], acc[m][1][2], acc[m][1][3], a0,a1,a2,a3, L0.z, L0.w);
                mma_bf16(acc[m][2][0], acc[m][2][1], acc[m][2][2], acc[m][2][3], a0,a1,a2,a3, L1.x, L1.y);
                mma_bf16(acc[m][3][0], acc[m][3][1], acc[m][3][2], acc[m][3][3], a0,a1,a2,a3, L1.z, L1.w);
                mma_bf16(acc[m][4][0], acc[m][4][1], acc[m][4][2], acc[m][4][3], a0,a1,a2,a3, L2.x, L2.y);
                mma_bf16(acc[m][5][0], acc[m][5][1], acc[m][5][2], acc[m][5][3], a0,a1,a2,a3, L2.z, L2.w);
                mma_bf16(acc[m][6][0], acc[m][6][1], acc[m][6][2], acc[m][6][3], a0,a1,a2,a3, L3.x, L3.y);
                mma_bf16(acc[m][7][0], acc[m][7][1], acc[m][7][2], acc[m][7][3], a0,a1,a2,a3, L3.z, L3.w);
            }
        }

        #pragma unroll
        for (int m = 0; m < 2; m++) {
            #pragma unroll
            for (int hh = 0; hh < 2; hh++) {
                int px = pxBase + m*16 + groupId + hh*8;
                __nv_bfloat16* op = outp + ((size_t)(bb*H + yOut)*W + x0 + px)*64 + quad*2;
                #pragma unroll
                for (int n = 0; n < 8; n++) {
                    float v0 = fmaxf(acc[m][n][hh*2 + 0], 0.f);
                    float v1 = fmaxf(acc[m][n][hh*2 + 1], 0.f);
                    *(__nv_bfloat162*)(op + n*8) = __floats2bfloat162_rn(v0, v1);
                }
            }
        }
    }
}

// =====================================================================
// bf16 implicit-GEMM conv (conv2/conv3), cp.async fills.
// __launch_bounds__(256,3): cap regs at ~85 -> 3 blocks/SM (24 warps).
// =====================================================================
#define SMB (4*130*PADB*2)

template<int KSTEPS, int NCHUNK, int CINTOT, int OSTR, bool RELU, bool FEAT>
__global__ __launch_bounds__(256, 3)
void gemm_bf16_k(const __nv_bfloat16* __restrict__ in, const uint32_t* __restrict__ gB,
                 const float* __restrict__ bias0, const float* __restrict__ bias1,
                 const float* __restrict__ bias2, __nv_bfloat16* __restrict__ out,
                 size_t inStride, size_t outStride)
{
    extern __shared__ __align__(16) char sAb[];
    constexpr int BSZ = NCHUNK*9*KSTEPS*256;

    const int z  = blockIdx.z;
    const int bb = z & 1;
    const int br = z >> 1;
    const float* bias = br == 0 ? bias0 : (br == 1 ? bias1 : bias2);
    in  += (size_t)br * inStride;
    out += (size_t)br * outStride;
    gB  += br * BSZ;
    const int outOff = FEAT ? br*32 : 0;

    const int x0 = blockIdx.x * 128;
    const int y0 = blockIdx.y * 2;
    const int tid = threadIdx.x;
    const int warp = tid >> 5, lane = tid & 31;
    const int warpRow = warp >> 2;
    const int pxBase  = (warp & 3) * 32;
    const int groupId = lane >> 2, quad = lane & 3;

    const uint32_t aLane = smem_u32(sAb) + (uint32_t)((lane & 15)*(PADB*2) + (lane >> 4)*16);

    float acc[2][4][4];
    #pragma unroll
    for (int n = 0; n < 4; n++) {
        float b0 = __ldg(&bias[n*8 + quad*2 + 0]);
        float b1 = __ldg(&bias[n*8 + quad*2 + 1]);
        #pragma unroll
        for (int m = 0; m < 2; m++) {
            acc[m][n][0] = b0; acc[m][n][1] = b1;
            acc[m][n][2] = b0; acc[m][n][3] = b1;
        }
    }

    #pragma unroll 1
    for (int ch = 0; ch < NCHUNK; ch++) {
        __syncthreads();
        #pragma unroll
        for (int r = 0; r < 4; r++) {
            int y = y0 - 1 + r;
            bool yin = (unsigned)y < (unsigned)H;
            for (int i = tid; i < 130*4; i += 256) {
                int px = i >> 2, v = i & 3;
                int x = x0 - 1 + px;
                bool inb = yin && ((unsigned)x < (unsigned)W);
                const __nv_bfloat16* src = in +
                    ((size_t)(bb*H + (inb ? y : 0))*W + (inb ? x : 0))*CINTOT + ch*32 + v*8;
                cp16(smem_u32(sAb + (size_t)(r*130 + px)*(PADB*2) + v*16), src, inb ? 16 : 0);
            }
        }
        cp_commit_wait();
        __syncthreads();

        #pragma unroll
        for (int dy = 0; dy < 3; dy++) {
            #pragma unroll
            for (int dx = 0; dx < 3; dx++) {
                const uint32_t aBase = aLane +
                    (uint32_t)(((warpRow + dy)*130 + pxBase + dx)*(PADB*2));
                const uint4* pb4 = (const uint4*)gB + ((ch*9 + dy*3 + dx)*KSTEPS)*64 + lane;
                #pragma unroll
                for (int kk = 0; kk < KSTEPS; kk++) {
                    uint4 L0 = __ldg(pb4 + kk*64);
                    uint4 L1 = __ldg(pb4 + kk*64 + 32);
                    #pragma unroll
                    for (int m = 0; m < 2; m++) {
                        uint32_t a0, a1, a2, a3;
                        ldmA(a0, a1, a2, a3, aBase + (uint32_t)(m*16*(PADB*2) + kk*32));
                        mma_bf16(acc[m][0][0], acc[m][0][1], acc[m][0][2], acc[m][0][3],
                                 a0, a1, a2, a3, L0.x, L0.y);
                        mma_bf16(acc[m][1][0], acc[m][1][1], acc[m][1][2], acc[m][1][3],
                                 a0, a1, a2, a3, L0.z, L0.w);
                        mma_bf16(acc[m][2][0], acc[m][2][1], acc[m][2][2], acc[m][2][3],
                                 a0, a1, a2, a3, L1.x, L1.y);
                        mma_bf16(acc[m][3][0], acc[m][3][1], acc[m][3][2], acc[m][3][3],
                                 a0, a1, a2, a3, L1.z, L1.w);
                    }
                }
            }
        }
    }

    const int yOut = y0 + warpRow;
    #pragma unroll
    for (int m = 0; m < 2; m++) {
        #pragma unroll
        for (int hh = 0; hh < 2; hh++) {
            int px = pxBase + m*16 + groupId + hh*8;
            __nv_bfloat16* op = out + ((size_t)(bb*H + yOut)*W + x0 + px)*OSTR + outOff + quad*2;
            #pragma unroll
            for (int n = 0; n < 4; n++) {
                float v0 = acc[m][n][hh*2 + 0];
                float v1 = acc[m][n][hh*2 + 1];
                if (RELU) { v0 = fmaxf(v0, 0.f); v1 = fmaxf(v1, 0.f); }
                *(__nv_bfloat162*)(op + n*8) = __floats2bfloat162_rn(v0, v1);
            }
        }
    }
}

// =====================================================================
// shifted-window attention: 2 windows/block (128 thr), f32x2 packed math
// =====================================================================
__global__ __launch_bounds__(128)
void attn_k(const __nv_bfloat16* __restrict__ feat, const float* __restrict__ pos,
            __nv_bfloat16* __restrict__ aout)
{
    __shared__ float sK[2][64][32];
    __shared__ float sV[2][64][32];
    __shared__ float sPos[225];

    const int bb = blockIdx.y;
    const int tid = threadIdx.x;
    const int sub = tid >> 6;           // which window half
    const int t64 = tid & 63;
    const int w   = blockIdx.x*2 + sub;
    const int wh = w / NWIN, ww = w - wh*NWIN;
    const int iy = t64 >> 3, ix = t64 & 7;
    const int sy = wh*8 + iy, sx = ww*8 + ix;
    int y = sy + 4; if (y >= H) y -= H;
    int x = sx + 4; if (x >= W) x -= W;

    for (int idx = t64; idx < 64*4; idx += 64) {
        int j = idx >> 2, part = idx & 3;
        int jy = j >> 3, jx = j & 7;
        int yy = wh*8 + jy + 4; if (yy >= H) yy -= H;
        int xx = ww*8 + jx + 4; if (xx >= W) xx -= W;
        const __nv_bfloat16* p = feat + ((size_t)(bb*H + yy)*W + xx)*96;
        uint4 uk = *(const uint4*)(p + 32 + part*8);
        uint4 uv = *(const uint4*)(p + 64 + part*8);
        const __nv_bfloat162* hk = (const __nv_bfloat162*)&uk;
        const __nv_bfloat162* hv = (const __nv_bfloat162*)&uv;
        #pragma unroll
        for (int t = 0; t < 4; t++) {
            float2 fk = __bfloat1622float2(hk[t]);
            float2 fv = __bfloat1622float2(hv[t]);
            sK[sub][j][part*8 + t*2 + 0] = fk.x;
            sK[sub][j][part*8 + t*2 + 1] = fk.y;
            sV[sub][j][part*8 + t*2 + 0] = fv.x;
            sV[sub][j][part*8 + t*2 + 1] = fv.y;
        }
    }
    for (int idx = tid; idx < 225; idx += 128) sPos[idx] = pos[idx];

    unsigned long long q2[16];
    {
        const __nv_bfloat16* fp = feat + ((size_t)(bb*H + y)*W + x)*96;
        #pragma unroll
        for (int part = 0; part < 4; part++) {
            uint4 u = *(const uint4*)(fp + part*8);
            const __nv_bfloat162* hq = (const __nv_bfloat162*)&u;
            #pragma unroll
            for (int t = 0; t < 4; t++) {
                float2 f = __bfloat1622float2(hq[t]);
                q2[part*4 + t] = pack2(f.x, f.y);
            }
        }
    }
    __syncthreads();

    const bool mR = (wh == NWIN-1);
    const bool mC = (ww == NWIN-1);
    const float scale = 0.35355339059327373f;
    const int posOff = (7 - iy)*15 + (7 - ix);

    __nv_bfloat16* op = aout + ((size_t)(bb*H + sy)*W + sx)*32;

    #pragma unroll 1
    for (int h = 0; h < 4; h++) {
        float lg[64];
        float mx = -1e30f;
        #pragma unroll
        for (int j = 0; j < 64; j++) {
            const int jy = j >> 3, jx = j & 7;
            const unsigned long long* kp = (const unsigned long long*)&sK[sub][j][h*8];
            unsigned long long d2 = fma2(q2[h*4+0], kp[0], 0ULL);
            d2 = fma2(q2[h*4+1], kp[1], d2);
            d2 = fma2(q2[h*4+2], kp[2], d2);
            d2 = fma2(q2[h*4+3], kp[3], d2);
            float l = (lo2(d2) + hi2(d2))*scale + sPos[jy*15 + jx + posOff];
            bool msk = (mR && ((iy >= 4) != (jy >= 4))) ||
                       (mC && ((ix >= 4) != (jx >= 4)));
            l = msk ? -1e30f : l;
            lg[j] = l;
            mx = fmaxf(mx, l);
        }
        float s = 0.f;
        #pragma unroll
        for (int j = 0; j < 64; j++) {
            float e = __expf(lg[j] - mx);
            lg[j] = e;
            s += e;
        }
        const float inv = 1.f / s;
        unsigned long long oh2[4];
        #pragma unroll
        for (int d = 0; d < 4; d++) oh2[d] = 0ULL;
        #pragma unroll
        for (int j = 0; j < 64; j++) {
            unsigned long long pp = pack2(lg[j], lg[j]);
            const unsigned long long* vp = (const unsigned long long*)&sV[sub][j][h*8];
            oh2[0] = fma2(pp, vp[0], oh2[0]);
            oh2[1] = fma2(pp, vp[1], oh2[1]);
            oh2[2] = fma2(pp, vp[2], oh2[2]);
            oh2[3] = fma2(pp, vp[3], oh2[3]);
        }
        #pragma unroll
        for (int d = 0; d < 4; d++)
            *(__nv_bfloat162*)(op + h*8 + d*2) =
                __floats2bfloat162_rn(lo2(oh2[d])*inv, hi2(oh2[d])*inv);
    }
}

// =====================================================================
// conv_out GEMM (32->3, 8 couts padded) + roll(+4,+4) + residual, fp32 out
// =====================================================================
__global__ __launch_bounds__(256, 3)
void convout_gemm_k(const __nv_bfloat16* __restrict__ in, const uint32_t* __restrict__ gB,
                    const float* __restrict__ bias, const float* __restrict__ xin,
                    float* __restrict__ out)
{
    extern __shared__ __align__(16) char sAb[];

    const int bb = blockIdx.z;
    const int x0 = blockIdx.x * 128;
    const int y0 = blockIdx.y * 2;
    const int tid = threadIdx.x;
    const int warp = tid >> 5, lane = tid & 31;
    const int warpRow = warp >> 2;
    const int pxBase  = (warp & 3) * 32;
    const int groupId = lane >> 2, quad = lane & 3;

    const uint32_t aLane = smem_u32(sAb) + (uint32_t)((lane & 15)*(PADB*2) + (lane >> 4)*16);

    const int co0 = quad*2, co1 = quad*2 + 1;
    float acc[2][4];
    {
        float b0 = co0 < 3 ? __ldg(&bias[co0]) : 0.f;
        float b1 = co1 < 3 ? __ldg(&bias[co1]) : 0.f;
        #pragma unroll
        for (int m = 0; m < 2; m++) {
            acc[m][0] = b0; acc[m][1] = b1;
            acc[m][2] = b0; acc[m][3] = b1;
        }
    }

    #pragma unroll
    for (int r = 0; r < 4; r++) {
        int y = y0 - 1 + r;
        bool yin = (unsigned)y < (unsigned)H;
        for (int i = tid; i < 130*4; i += 256) {
            int px = i >> 2, v = i & 3;
            int x = x0 - 1 + px;
            bool inb = yin && ((unsigned)x < (unsigned)W);
            const __nv_bfloat16* src = in +
                ((size_t)(bb*H + (inb ? y : 0))*W + (inb ? x : 0))*32 + v*8;
            cp16(smem_u32(sAb + (size_t)(r*130 + px)*(PADB*2) + v*16), src, inb ? 16 : 0);
        }
    }
    cp_commit_wait();
    __syncthreads();

    #pragma unroll
    for (int dy = 0; dy < 3; dy++) {
        #pragma unroll
        for (int dx = 0; dx < 3; dx++) {
            const uint32_t aBase = aLane +
                (uint32_t)(((warpRow + dy)*130 + pxBase + dx)*(PADB*2));
            const uint2* pb2 = (const uint2*)gB + (dy*3 + dx)*2*32 + lane;
            #pragma unroll
            for (int kk = 0; kk < 2; kk++) {
                uint2 L = __ldg(pb2 + kk*32);
                #pragma unroll
                for (int m = 0; m < 2; m++) {
                    uint32_t a0, a1, a2, a3;
                    ldmA(a0, a1, a2, a3, aBase + (uint32_t)(m*16*(PADB*2) + kk*32));
                    mma_bf16(acc[m][0], acc[m][1], acc[m][2], acc[m][3],
                             a0, a1, a2, a3, L.x, L.y);
                }
            }
        }
    }

    const int gy = y0 + warpRow;
    int oy = gy + 4; if (oy >= H) oy -= H;
    #pragma unroll
    for (int m = 0; m < 2; m++) {
        #pragma unroll
        for (int hh = 0; hh < 2; hh++) {
            int gx = x0 + pxBase + m*16 + groupId + hh*8;
            int ox = gx + 4; if (ox >= W) ox -= W;
            if (co0 < 3) {
                size_t idx = ((size_t)(bb*3 + co0)*H + oy)*W + ox;
                out[idx] = xin[idx] + acc[m][hh*2 + 0];
            }
            if (co1 < 3) {
                size_t idx = ((size_t)(bb*3 + co1)*H + oy)*W + ox;
                out[idx] = xin[idx] + acc[m][hh*2 + 1];
            }
        }
    }
}

// ---------------- launcher ----------------
extern "C" void kernel_launch(void* const* d_in, const int* in_sizes, int n_in,
                              void* d_out, int out_size)
{
    (void)in_sizes; (void)n_in; (void)out_size;
    const float* x   = (const float*)d_in[0];
    const float* wo  = (const float*)d_in[19];
    const float* bo  = (const float*)d_in[20];
    const float* pos = (const float*)d_in[21];
    float* out = (float*)d_out;

    __nv_bfloat16 *h1, *h2, *feat, *aout;
    uint32_t *bf1, *bf2, *bf3, *bfo;
    cudaGetSymbolAddress((void**)&h1,   g_h1);
    cudaGetSymbolAddress((void**)&h2,   g_h2);
    cudaGetSymbolAddress((void**)&feat, g_feat);
    cudaGetSymbolAddress((void**)&aout, g_aout);
    cudaGetSymbolAddress((void**)&bf1,  g_bf1);
    cudaGetSymbolAddress((void**)&bf2,  g_bf2);
    cudaGetSymbolAddress((void**)&bf3,  g_bf3);
    cudaGetSymbolAddress((void**)&bfo,  g_bfo);

    // single merged B prep (45696 elements)
    prep_all_k<<<179, 256>>>(
        (const float*)d_in[1], (const float*)d_in[7],  (const float*)d_in[13],
        (const float*)d_in[3], (const float*)d_in[9],  (const float*)d_in[15],
        (const float*)d_in[5], (const float*)d_in[11], (const float*)d_in[17],
        wo, bf1, bf2, bf3, bfo);

    dim3 g1(W/128, H/2, BATCH);     // conv1 fused: z = bb
    dim3 gg(W/128, H/2, BATCH*3);   // conv2/conv3: z = br*2 + bb

    conv1_im2col_k<<<g1, 256>>>(
        x, bf1,
        (const float*)d_in[2], (const float*)d_in[8], (const float*)d_in[14], h1);
    gemm_bf16_k<2, 2, 64, 32, true,  false><<<gg, 256, SMB>>>(
        h1, bf2,
        (const float*)d_in[4], (const float*)d_in[10], (const float*)d_in[16],
        h2, H1SZ, H2SZ);
    gemm_bf16_k<2, 1, 32, 96, false, true ><<<gg, 256, SMB>>>(
        h2, bf3,
        (const float*)d_in[6], (const float*)d_in[12], (const float*)d_in[18],
        feat, H2SZ, 0);

    attn_k<<<dim3(NWIN*NWIN/2, BATCH), 128>>>(feat, pos, aout);
    convout_gemm_k<<<g1, 256, SMB>>>(aout, bfo, bo, x, out);
}

// round 14
// speedup vs baseline: 2.2856x; 1.0404x over previous
#include <cuda_runtime.h>
#include <cuda_bf16.h>
#include <cstdint>
#include <cstddef>

#define H 384
#define W 384
#define BATCH 2
#define NWIN 48

#define H1SZ ((size_t)BATCH*H*W*64)   // elements per branch (bf16)
#define H2SZ ((size_t)BATCH*H*W*32)

// ---------------- scratch ----------------
__device__ __nv_bfloat16 g_h1[3*H1SZ];
__device__ __nv_bfloat16 g_h2[3*H2SZ];
__device__ __nv_bfloat16 g_feat[(size_t)BATCH*H*W*96];
__device__ __nv_bfloat16 g_aout[(size_t)BATCH*H*W*32];   // channel-last, shifted space
__device__ uint32_t g_bf1[3*1024];     // conv1 B frags (bf16x2, im2col K=32)
__device__ uint32_t g_bf2[3*9216];     // conv2 B frags
__device__ uint32_t g_bf3[3*4608];     // conv3 B frags
__device__ uint32_t g_bfo[1152];       // conv_out B frags (8 couts, 3 real)

// ---------------- helpers ----------------
__device__ __forceinline__ void mma_bf16(float& c0, float& c1, float& c2, float& c3,
                                         uint32_t a0, uint32_t a1, uint32_t a2, uint32_t a3,
                                         uint32_t b0, uint32_t b1) {
    asm volatile("mma.sync.aligned.m16n8k16.row.col.f32.bf16.bf16.f32 "
                 "{%0,%1,%2,%3}, {%4,%5,%6,%7}, {%8,%9}, {%0,%1,%2,%3};"
                 : "+f"(c0), "+f"(c1), "+f"(c2), "+f"(c3)
                 : "r"(a0), "r"(a1), "r"(a2), "r"(a3), "r"(b0), "r"(b1));
}
__device__ __forceinline__ void ldmA(uint32_t& r0, uint32_t& r1, uint32_t& r2, uint32_t& r3,
                                     uint32_t addr) {
    asm volatile("ldmatrix.sync.aligned.m8n8.x4.shared.b16 {%0,%1,%2,%3}, [%4];"
                 : "=r"(r0), "=r"(r1), "=r"(r2), "=r"(r3) : "r"(addr));
}
__device__ __forceinline__ uint32_t smem_u32(const void* p) {
    return (uint32_t)__cvta_generic_to_shared(p);
}
__device__ __forceinline__ void cp16(uint32_t dst, const void* src, int sz) {
    asm volatile("cp.async.cg.shared.global [%0], [%1], 16, %2;"
                 :: "r"(dst), "l"(src), "r"(sz));
}
__device__ __forceinline__ void cp4(uint32_t dst, const void* src, int sz) {
    asm volatile("cp.async.ca.shared.global [%0], [%1], 4, %2;"
                 :: "r"(dst), "l"(src), "r"(sz));
}
__device__ __forceinline__ void cp_commit_wait() {
    asm volatile("cp.async.commit_group;");
    asm volatile("cp.async.wait_group 0;");
}
// packed fp32x2
__device__ __forceinline__ unsigned long long pack2(float lo, float hi) {
    unsigned long long r;
    asm("mov.b64 %0, {%1, %2};" : "=l"(r) : "f"(lo), "f"(hi));
    return r;
}
__device__ __forceinline__ unsigned long long fma2(unsigned long long a,
                                                   unsigned long long b,
                                                   unsigned long long c) {
    unsigned long long d;
    asm("fma.rn.f32x2 %0, %1, %2, %3;" : "=l"(d) : "l"(a), "l"(b), "l"(c));
    return d;
}
__device__ __forceinline__ float lo2(unsigned long long v) {
    return __uint_as_float((unsigned)(v & 0xffffffffULL));
}
__device__ __forceinline__ float hi2(unsigned long long v) {
    return __uint_as_float((unsigned)(v >> 32));
}

// =====================================================================
// merged B prep: bf1 (3x1024) | bf2 (3x9216) | bf3 (3x4608) | bfo (1152)
// =====================================================================
__global__ void prep_all_k(const float* __restrict__ w1a, const float* __restrict__ w1b,
                           const float* __restrict__ w1c,
                           const float* __restrict__ w2a, const float* __restrict__ w2b,
                           const float* __restrict__ w2c,
                           const float* __restrict__ w3a, const float* __restrict__ w3b,
                           const float* __restrict__ w3c,
                           const float* __restrict__ wo,
                           uint32_t* __restrict__ bf1, uint32_t* __restrict__ bf2,
                           uint32_t* __restrict__ bf3, uint32_t* __restrict__ bfo)
{
    int gid = blockIdx.x*256 + threadIdx.x;

    if (gid < 3072) {                                   // conv1: im2col K=32 (27 real)
        int br = gid / 1024, idx = gid - br*1024;
        const float* wt = br == 0 ? w1a : (br == 1 ? w1b : w1c);
        int r    = idx & 3;
        int lane = (idx >> 2) & 31;
        int half = (idx >> 7) & 3;
        int kk   = idx >> 9;
        int n    = half*2 + (r >> 1);
        int breg = r & 1;
        int k0 = kk*16 + (lane & 3)*2 + breg*8;
        int co = n*8 + (lane >> 2);
        float v0 = 0.f, v1 = 0.f;
        if (k0 + 0 < 27) v0 = wt[(co*3 + (k0+0)/9)*9 + (k0+0)%9];
        if (k0 + 1 < 27) v1 = wt[(co*3 + (k0+1)/9)*9 + (k0+1)%9];
        __nv_bfloat162 pk = __floats2bfloat162_rn(v0, v1);
        bf1[gid] = *(uint32_t*)&pk;
        return;
    }
    gid -= 3072;
    if (gid < 27648) {                                  // conv2: CIN=64
        int br = gid / 9216, idx = gid - br*9216;
        const float* wt = br == 0 ? w2a : (br == 1 ? w2b : w2c);
        int r    = idx & 3;
        int lane = (idx >> 2) & 31;
        int half = (idx >> 7) & 1;
        int rest = idx >> 8;
        int kk   = rest & 1;
        int rest2 = rest >> 1;
        int dydx = rest2 % 9;
        int ch   = rest2 / 9;
        int n    = half*2 + (r >> 1);
        int breg = r & 1;
        int ci = ch*32 + kk*16 + (lane & 3)*2 + breg*8;
        int co = n*8 + (lane >> 2);
        __nv_bfloat162 pk = __floats2bfloat162_rn(
            wt[(co*64 + ci + 0)*9 + dydx], wt[(co*64 + ci + 1)*9 + dydx]);
        bf2[br*9216 + idx] = *(uint32_t*)&pk;
        return;
    }
    gid -= 27648;
    if (gid < 13824) {                                  // conv3: CIN=32
        int br = gid / 4608, idx = gid - br*4608;
        const float* wt = br == 0 ? w3a : (br == 1 ? w3b : w3c);
        int r    = idx & 3;
        int lane = (idx >> 2) & 31;
        int half = (idx >> 7) & 1;
        int rest = idx >> 8;
        int kk   = rest & 1;
        int dydx = rest >> 1;
        int n    = half*2 + (r >> 1);
        int breg = r & 1;
        int ci = kk*16 + (lane & 3)*2 + breg*8;
        int co = n*8 + (lane >> 2);
        __nv_bfloat162 pk = __floats2bfloat162_rn(
            wt[(co*32 + ci + 0)*9 + dydx], wt[(co*32 + ci + 1)*9 + dydx]);
        bf3[br*4608 + idx] = *(uint32_t*)&pk;
        return;
    }
    gid -= 13824;
    if (gid < 1152) {                                   // conv_out: 8 couts (3 real)
        int idx = gid;
        int breg = idx & 1;
        int lane = (idx >> 1) & 31;
        int kk   = (idx >> 6) & 1;
        int dydx = idx >> 7;
        int ci = kk*16 + (lane & 3)*2 + breg*8;
        int co = lane >> 2;
        float v0 = 0.f, v1 = 0.f;
        if (co < 3) {
            v0 = wo[(co*32 + ci + 0)*9 + dydx];
            v1 = wo[(co*32 + ci + 1)*9 + dydx];
        }
        __nv_bfloat162 pk = __floats2bfloat162_rn(v0, v1);
        bfo[idx] = *(uint32_t*)&pk;
    }
}

// =====================================================================
// conv1 fused: 3->64 x 3 branches. One fill + one im2col, 3 mainloops.
// =====================================================================
#define PADB 40

__global__ __launch_bounds__(256, 2)
void conv1_im2col_k(const float* __restrict__ in, const uint32_t* __restrict__ gB,
                    const float* __restrict__ bias0, const float* __restrict__ bias1,
                    const float* __restrict__ bias2, __nv_bfloat16* __restrict__ out)
{
    __shared__ float sRaw[3][4][132];
    __shared__ __align__(16) __nv_bfloat16 sA[256][PADB];

    const int bb = blockIdx.z;
    const int x0 = blockIdx.x * 128;
    const int y0 = blockIdx.y * 2;
    const int tid = threadIdx.x;
    const int warp = tid >> 5, lane = tid & 31;
    const int warpRow = warp >> 2;
    const int pxBase  = (warp & 3) * 32;
    const int groupId = lane >> 2, quad = lane & 3;

    for (int i = tid; i < 3*4*130; i += 256) {
        int ci = i / 520;
        int r2 = i - ci*520;
        int rr = r2 / 130;
        int xx = r2 - rr*130;
        int y = y0 - 1 + rr, x = x0 - 1 + xx;
        bool inb = ((unsigned)y < (unsigned)H) && ((unsigned)x < (unsigned)W);
        const float* src = in + ((size_t)(bb*3 + ci)*H + (inb ? y : 0))*W + (inb ? x : 0);
        cp4(smem_u32(&sRaw[ci][rr][xx]), src, inb ? 4 : 0);
    }
    cp_commit_wait();
    __syncthreads();

    {
        int r = tid >> 7, px = tid & 127;
        float vals[32];
        #pragma unroll
        for (int ci = 0; ci < 3; ci++)
            #pragma unroll
            for (int dy = 0; dy < 3; dy++)
                #pragma unroll
                for (int dx = 0; dx < 3; dx++)
                    vals[ci*9 + dy*3 + dx] = sRaw[ci][r + dy][px + dx];
        #pragma unroll
        for (int k = 27; k < 32; k++) vals[k] = 0.f;
        uint32_t pk[16];
        #pragma unroll
        for (int t = 0; t < 16; t++) {
            __nv_bfloat162 p = __floats2bfloat162_rn(vals[2*t], vals[2*t+1]);
            pk[t] = *(uint32_t*)&p;
        }
        uint4* dstp = (uint4*)&sA[tid][0];
        dstp[0] = make_uint4(pk[0],  pk[1],  pk[2],  pk[3]);
        dstp[1] = make_uint4(pk[4],  pk[5],  pk[6],  pk[7]);
        dstp[2] = make_uint4(pk[8],  pk[9],  pk[10], pk[11]);
        dstp[3] = make_uint4(pk[12], pk[13], pk[14], pk[15]);
    }
    __syncthreads();

    const uint32_t aLane = smem_u32(sA) +
        (uint32_t)((warpRow*128 + pxBase + (lane & 15))*(PADB*2) + (lane >> 4)*16);
    const int yOut = y0 + warpRow;

    #pragma unroll 1
    for (int br = 0; br < 3; br++) {
        const float* bias = br == 0 ? bias0 : (br == 1 ? bias1 : bias2);
        const uint4* pb4 = (const uint4*)(gB + br*1024) + lane;
        __nv_bfloat16* outp = out + (size_t)br * H1SZ;

        float acc[2][8][4];
        #pragma unroll
        for (int n = 0; n < 8; n++) {
            float b0 = __ldg(&bias[n*8 + quad*2 + 0]);
            float b1 = __ldg(&bias[n*8 + quad*2 + 1]);
            #pragma unroll
            for (int m = 0; m < 2; m++) {
                acc[m][n][0] = b0; acc[m][n][1] = b1;
                acc[m][n][2] = b0; acc[m][n][3] = b1;
            }
        }

        #pragma unroll
        for (int kk = 0; kk < 2; kk++) {
            uint4 L0 = __ldg(pb4 + kk*128);
            uint4 L1 = __ldg(pb4 + kk*128 + 32);
            uint4 L2 = __ldg(pb4 + kk*128 + 64);
            uint4 L3 = __ldg(pb4 + kk*128 + 96);
            #pragma unroll
            for (int m = 0; m < 2; m++) {
                uint32_t a0, a1, a2, a3;
                ldmA(a0, a1, a2, a3, aLane + (uint32_t)(m*16*(PADB*2) + kk*32));
                mma_bf16(acc[m][0][0], acc[m][0][1], acc[m][0][2], acc[m][0][3], a0,a1,a2,a3, L0.x, L0.y);
                mma_bf16(acc[m][1][0], acc[m][1][1], acc[m][1][2], acc[m][1][3], a0,a1,a2,a3, L0.z, L0.w);
                mma_bf16(acc[m][2][0], acc[m][2][1], acc[m][2][2], acc[m][2][3], a0,a1,a2,a3, L1.x, L1.y);
                mma_bf16(acc[m][3][0], acc[m][3][1], acc[m][3][2], acc[m][3][3], a0,a1,a2,a3, L1.z, L1.w);
                mma_bf16(acc[m][4][0], acc[m][4][1], acc[m][4][2], acc[m][4][3], a0,a1,a2,a3, L2.x, L2.y);
                mma_bf16(acc[m][5][0], acc[m][5][1], acc[m][5][2], acc[m][5][3], a0,a1,a2,a3, L2.z, L2.w);
                mma_bf16(acc[m][6][0], acc[m][6][1], acc[m][6][2], acc[m][6][3], a0,a1,a2,a3, L3.x, L3.y);
                mma_bf16(acc[m][7][0], acc[m][7][1], acc[m][7][2], acc[m][7][3], a0,a1,a2,a3, L3.z, L3.w);
            }
        }

        #pragma unroll
        for (int m = 0; m < 2; m++) {
            #pragma unroll
            for (int hh = 0; hh < 2; hh++) {
                int px = pxBase + m*16 + groupId + hh*8;
                __nv_bfloat16* op = outp + ((size_t)(bb*H + yOut)*W + x0 + px)*64 + quad*2;
                #pragma unroll
                for (int n = 0; n < 8; n++) {
                    float v0 = fmaxf(acc[m][n][hh*2 + 0], 0.f);
                    float v1 = fmaxf(acc[m][n][hh*2 + 1], 0.f);
                    *(__nv_bfloat162*)(op + n*8) = __floats2bfloat162_rn(v0, v1);
                }
            }
        }
    }
}

// =====================================================================
// bf16 implicit-GEMM conv (conv2/conv3): 4 rows x 128 px per block,
// 8 warps = 2/row x 4 rows, each warp 64 px (4 m16 tiles). Slab 6 rows.
// =====================================================================
#define SMB4 (6*130*PADB*2)
#define SMB  (4*130*PADB*2)

template<int KSTEPS, int NCHUNK, int CINTOT, int OSTR, bool RELU, bool FEAT>
__global__ __launch_bounds__(256, 2)
void gemm_bf16_k(const __nv_bfloat16* __restrict__ in, const uint32_t* __restrict__ gB,
                 const float* __restrict__ bias0, const float* __restrict__ bias1,
                 const float* __restrict__ bias2, __nv_bfloat16* __restrict__ out,
                 size_t inStride, size_t outStride)
{
    extern __shared__ __align__(16) char sAb[];
    constexpr int BSZ = NCHUNK*9*KSTEPS*256;

    const int z  = blockIdx.z;
    const int bb = z & 1;
    const int br = z >> 1;
    const float* bias = br == 0 ? bias0 : (br == 1 ? bias1 : bias2);
    in  += (size_t)br * inStride;
    out += (size_t)br * outStride;
    gB  += br * BSZ;
    const int outOff = FEAT ? br*32 : 0;

    const int x0 = blockIdx.x * 128;
    const int y0 = blockIdx.y * 4;
    const int tid = threadIdx.x;
    const int warp = tid >> 5, lane = tid & 31;
    const int warpRow = warp >> 1;          // 0..3
    const int pxBase  = (warp & 1) * 64;    // 0 or 64
    const int groupId = lane >> 2, quad = lane & 3;

    const uint32_t aLane = smem_u32(sAb) + (uint32_t)((lane & 15)*(PADB*2) + (lane >> 4)*16);

    float acc[4][4][4];
    #pragma unroll
    for (int n = 0; n < 4; n++) {
        float b0 = __ldg(&bias[n*8 + quad*2 + 0]);
        float b1 = __ldg(&bias[n*8 + quad*2 + 1]);
        #pragma unroll
        for (int m = 0; m < 4; m++) {
            acc[m][n][0] = b0; acc[m][n][1] = b1;
            acc[m][n][2] = b0; acc[m][n][3] = b1;
        }
    }

    #pragma unroll 1
    for (int ch = 0; ch < NCHUNK; ch++) {
        __syncthreads();
        #pragma unroll
        for (int r = 0; r < 6; r++) {
            int y = y0 - 1 + r;
            bool yin = (unsigned)y < (unsigned)H;
            for (int i = tid; i < 130*4; i += 256) {
                int px = i >> 2, v = i & 3;
                int x = x0 - 1 + px;
                bool inb = yin && ((unsigned)x < (unsigned)W);
                const __nv_bfloat16* src = in +
                    ((size_t)(bb*H + (inb ? y : 0))*W + (inb ? x : 0))*CINTOT + ch*32 + v*8;
                cp16(smem_u32(sAb + (size_t)(r*130 + px)*(PADB*2) + v*16), src, inb ? 16 : 0);
            }
        }
        cp_commit_wait();
        __syncthreads();

        #pragma unroll
        for (int dy = 0; dy < 3; dy++) {
            #pragma unroll
            for (int dx = 0; dx < 3; dx++) {
                const uint32_t aBase = aLane +
                    (uint32_t)(((warpRow + dy)*130 + pxBase + dx)*(PADB*2));
                const uint4* pb4 = (const uint4*)gB + ((ch*9 + dy*3 + dx)*KSTEPS)*64 + lane;
                #pragma unroll
                for (int kk = 0; kk < KSTEPS; kk++) {
                    uint4 L0 = __ldg(pb4 + kk*64);
                    uint4 L1 = __ldg(pb4 + kk*64 + 32);
                    #pragma unroll
                    for (int m = 0; m < 4; m++) {
                        uint32_t a0, a1, a2, a3;
                        ldmA(a0, a1, a2, a3, aBase + (uint32_t)(m*16*(PADB*2) + kk*32));
                        mma_bf16(acc[m][0][0], acc[m][0][1], acc[m][0][2], acc[m][0][3],
                                 a0, a1, a2, a3, L0.x, L0.y);
                        mma_bf16(acc[m][1][0], acc[m][1][1], acc[m][1][2], acc[m][1][3],
                                 a0, a1, a2, a3, L0.z, L0.w);
                        mma_bf16(acc[m][2][0], acc[m][2][1], acc[m][2][2], acc[m][2][3],
                                 a0, a1, a2, a3, L1.x, L1.y);
                        mma_bf16(acc[m][3][0], acc[m][3][1], acc[m][3][2], acc[m][3][3],
                                 a0, a1, a2, a3, L1.z, L1.w);
                    }
                }
            }
        }
    }

    const int yOut = y0 + warpRow;
    #pragma unroll
    for (int m = 0; m < 4; m++) {
        #pragma unroll
        for (int hh = 0; hh < 2; hh++) {
            int px = pxBase + m*16 + groupId + hh*8;
            __nv_bfloat16* op = out + ((size_t)(bb*H + yOut)*W + x0 + px)*OSTR + outOff + quad*2;
            #pragma unroll
            for (int n = 0; n < 4; n++) {
                float v0 = acc[m][n][hh*2 + 0];
                float v1 = acc[m][n][hh*2 + 1];
                if (RELU) { v0 = fmaxf(v0, 0.f); v1 = fmaxf(v1, 0.f); }
                *(__nv_bfloat162*)(op + n*8) = __floats2bfloat162_rn(v0, v1);
            }
        }
    }
}

// =====================================================================
// shifted-window attention: 2 windows/block (128 thr), f32x2 packed math
// =====================================================================
__global__ __launch_bounds__(128)
void attn_k(const __nv_bfloat16* __restrict__ feat, const float* __restrict__ pos,
            __nv_bfloat16* __restrict__ aout)
{
    __shared__ float sK[2][64][32];
    __shared__ float sV[2][64][32];
    __shared__ float sPos[225];

    const int bb = blockIdx.y;
    const int tid = threadIdx.x;
    const int sub = tid >> 6;           // which window half
    const int t64 = tid & 63;
    const int w   = blockIdx.x*2 + sub;
    const int wh = w / NWIN, ww = w - wh*NWIN;
    const int iy = t64 >> 3, ix = t64 & 7;
    const int sy = wh*8 + iy, sx = ww*8 + ix;
    int y = sy + 4; if (y >= H) y -= H;
    int x = sx + 4; if (x >= W) x -= W;

    for (int idx = t64; idx < 64*4; idx += 64) {
        int j = idx >> 2, part = idx & 3;
        int jy = j >> 3, jx = j & 7;
        int yy = wh*8 + jy + 4; if (yy >= H) yy -= H;
        int xx = ww*8 + jx + 4; if (xx >= W) xx -= W;
        const __nv_bfloat16* p = feat + ((size_t)(bb*H + yy)*W + xx)*96;
        uint4 uk = *(const uint4*)(p + 32 + part*8);
        uint4 uv = *(const uint4*)(p + 64 + part*8);
        const __nv_bfloat162* hk = (const __nv_bfloat162*)&uk;
        const __nv_bfloat162* hv = (const __nv_bfloat162*)&uv;
        #pragma unroll
        for (int t = 0; t < 4; t++) {
            float2 fk = __bfloat1622float2(hk[t]);
            float2 fv = __bfloat1622float2(hv[t]);
            sK[sub][j][part*8 + t*2 + 0] = fk.x;
            sK[sub][j][part*8 + t*2 + 1] = fk.y;
            sV[sub][j][part*8 + t*2 + 0] = fv.x;
            sV[sub][j][part*8 + t*2 + 1] = fv.y;
        }
    }
    for (int idx = tid; idx < 225; idx += 128) sPos[idx] = pos[idx];

    unsigned long long q2[16];
    {
        const __nv_bfloat16* fp = feat + ((size_t)(bb*H + y)*W + x)*96;
        #pragma unroll
        for (int part = 0; part < 4; part++) {
            uint4 u = *(const uint4*)(fp + part*8);
            const __nv_bfloat162* hq = (const __nv_bfloat162*)&u;
            #pragma unroll
            for (int t = 0; t < 4; t++) {
                float2 f = __bfloat1622float2(hq[t]);
                q2[part*4 + t] = pack2(f.x, f.y);
            }
        }
    }
    __syncthreads();

    const bool mR = (wh == NWIN-1);
    const bool mC = (ww == NWIN-1);
    const float scale = 0.35355339059327373f;
    const int posOff = (7 - iy)*15 + (7 - ix);

    __nv_bfloat16* op = aout + ((size_t)(bb*H + sy)*W + sx)*32;

    #pragma unroll 1
    for (int h = 0; h < 4; h++) {
        float lg[64];
        float mx = -1e30f;
        #pragma unroll
        for (int j = 0; j < 64; j++) {
            const int jy = j >> 3, jx = j & 7;
            const unsigned long long* kp = (const unsigned long long*)&sK[sub][j][h*8];
            unsigned long long d2 = fma2(q2[h*4+0], kp[0], 0ULL);
            d2 = fma2(q2[h*4+1], kp[1], d2);
            d2 = fma2(q2[h*4+2], kp[2], d2);
            d2 = fma2(q2[h*4+3], kp[3], d2);
            float l = (lo2(d2) + hi2(d2))*scale + sPos[jy*15 + jx + posOff];
            bool msk = (mR && ((iy >= 4) != (jy >= 4))) ||
                       (mC && ((ix >= 4) != (jx >= 4)));
            l = msk ? -1e30f : l;
            lg[j] = l;
            mx = fmaxf(mx, l);
        }
        float s = 0.f;
        #pragma unroll
        for (int j = 0; j < 64; j++) {
            float e = __expf(lg[j] - mx);
            lg[j] = e;
            s += e;
        }
        const float inv = 1.f / s;
        unsigned long long oh2[4];
        #pragma unroll
        for (int d = 0; d < 4; d++) oh2[d] = 0ULL;
        #pragma unroll
        for (int j = 0; j < 64; j++) {
            unsigned long long pp = pack2(lg[j], lg[j]);
            const unsigned long long* vp = (const unsigned long long*)&sV[sub][j][h*8];
            oh2[0] = fma2(pp, vp[0], oh2[0]);
            oh2[1] = fma2(pp, vp[1], oh2[1]);
            oh2[2] = fma2(pp, vp[2], oh2[2]);
            oh2[3] = fma2(pp, vp[3], oh2[3]);
        }
        #pragma unroll
        for (int d = 0; d < 4; d++)
            *(__nv_bfloat162*)(op + h*8 + d*2) =
                __floats2bfloat162_rn(lo2(oh2[d])*inv, hi2(oh2[d])*inv);
    }
}

// =====================================================================
// conv_out GEMM (32->3, 8 couts padded) + roll(+4,+4) + residual, fp32 out
// (2-row tile, unchanged from R13)
// =====================================================================
__global__ __launch_bounds__(256, 3)
void convout_gemm_k(const __nv_bfloat16* __restrict__ in, const uint32_t* __restrict__ gB,
                    const float* __restrict__ bias, const float* __restrict__ xin,
                    float* __restrict__ out)
{
    extern __shared__ __align__(16) char sAb[];

    const int bb = blockIdx.z;
    const int x0 = blockIdx.x * 128;
    const int y0 = blockIdx.y * 2;
    const int tid = threadIdx.x;
    const int warp = tid >> 5, lane = tid & 31;
    const int warpRow = warp >> 2;
    const int pxBase  = (warp & 3) * 32;
    const int groupId = lane >> 2, quad = lane & 3;

    const uint32_t aLane = smem_u32(sAb) + (uint32_t)((lane & 15)*(PADB*2) + (lane >> 4)*16);

    const int co0 = quad*2, co1 = quad*2 + 1;
    float acc[2][4];
    {
        float b0 = co0 < 3 ? __ldg(&bias[co0]) : 0.f;
        float b1 = co1 < 3 ? __ldg(&bias[co1]) : 0.f;
        #pragma unroll
        for (int m = 0; m < 2; m++) {
            acc[m][0] = b0; acc[m][1] = b1;
            acc[m][2] = b0; acc[m][3] = b1;
        }
    }

    #pragma unroll
    for (int r = 0; r < 4; r++) {
        int y = y0 - 1 + r;
        bool yin = (unsigned)y < (unsigned)H;
        for (int i = tid; i < 130*4; i += 256) {
            int px = i >> 2, v = i & 3;
            int x = x0 - 1 + px;
            bool inb = yin && ((unsigned)x < (unsigned)W);
            const __nv_bfloat16* src = in +
                ((size_t)(bb*H + (inb ? y : 0))*W + (inb ? x : 0))*32 + v*8;
            cp16(smem_u32(sAb + (size_t)(r*130 + px)*(PADB*2) + v*16), src, inb ? 16 : 0);
        }
    }
    cp_commit_wait();
    __syncthreads();

    #pragma unroll
    for (int dy = 0; dy < 3; dy++) {
        #pragma unroll
        for (int dx = 0; dx < 3; dx++) {
            const uint32_t aBase = aLane +
                (uint32_t)(((warpRow + dy)*130 + pxBase + dx)*(PADB*2));
            const uint2* pb2 = (const uint2*)gB + (dy*3 + dx)*2*32 + lane;
            #pragma unroll
            for (int kk = 0; kk < 2; kk++) {
                uint2 L = __ldg(pb2 + kk*32);
                #pragma unroll
                for (int m = 0; m < 2; m++) {
                    uint32_t a0, a1, a2, a3;
                    ldmA(a0, a1, a2, a3, aBase + (uint32_t)(m*16*(PADB*2) + kk*32));
                    mma_bf16(acc[m][0], acc[m][1], acc[m][2], acc[m][3],
                             a0, a1, a2, a3, L.x, L.y);
                }
            }
        }
    }

    const int gy = y0 + warpRow;
    int oy = gy + 4; if (oy >= H) oy -= H;
    #pragma unroll
    for (int m = 0; m < 2; m++) {
        #pragma unroll
        for (int hh = 0; hh < 2; hh++) {
            int gx = x0 + pxBase + m*16 + groupId + hh*8;
            int ox = gx + 4; if (ox >= W) ox -= W;
            if (co0 < 3) {
                size_t idx = ((size_t)(bb*3 + co0)*H + oy)*W + ox;
                out[idx] = xin[idx] + acc[m][hh*2 + 0];
            }
            if (co1 < 3) {
                size_t idx = ((size_t)(bb*3 + co1)*H + oy)*W + ox;
                out[idx] = xin[idx] + acc[m][hh*2 + 1];
            }
        }
    }
}

// ---------------- launcher ----------------
extern "C" void kernel_launch(void* const* d_in, const int* in_sizes, int n_in,
                              void* d_out, int out_size)
{
    (void)in_sizes; (void)n_in; (void)out_size;
    const float* x   = (const float*)d_in[0];
    const float* wo  = (const float*)d_in[19];
    const float* bo  = (const float*)d_in[20];
    const float* pos = (const float*)d_in[21];
    float* out = (float*)d_out;

    __nv_bfloat16 *h1, *h2, *feat, *aout;
    uint32_t *bf1, *bf2, *bf3, *bfo;
    cudaGetSymbolAddress((void**)&h1,   g_h1);
    cudaGetSymbolAddress((void**)&h2,   g_h2);
    cudaGetSymbolAddress((void**)&feat, g_feat);
    cudaGetSymbolAddress((void**)&aout, g_aout);
    cudaGetSymbolAddress((void**)&bf1,  g_bf1);
    cudaGetSymbolAddress((void**)&bf2,  g_bf2);
    cudaGetSymbolAddress((void**)&bf3,  g_bf3);
    cudaGetSymbolAddress((void**)&bfo,  g_bfo);

    // 6-row slabs exceed 48KB default dynamic smem limit
    cudaFuncSetAttribute((const void*)gemm_bf16_k<2,2,64,32,true,false>,
                         cudaFuncAttributeMaxDynamicSharedMemorySize, SMB4);
    cudaFuncSetAttribute((const void*)gemm_bf16_k<2,1,32,96,false,true>,
                         cudaFuncAttributeMaxDynamicSharedMemorySize, SMB4);

    // single merged B prep (45696 elements)
    prep_all_k<<<179, 256>>>(
        (const float*)d_in[1], (const float*)d_in[7],  (const float*)d_in[13],
        (const float*)d_in[3], (const float*)d_in[9],  (const float*)d_in[15],
        (const float*)d_in[5], (const float*)d_in[11], (const float*)d_in[17],
        wo, bf1, bf2, bf3, bfo);

    dim3 g1(W/128, H/2, BATCH);     // conv1 fused: z = bb
    dim3 gg(W/128, H/4, BATCH*3);   // conv2/conv3 4-row tiles: z = br*2 + bb

    conv1_im2col_k<<<g1, 256>>>(
        x, bf1,
        (const float*)d_in[2], (const float*)d_in[8], (const float*)d_in[14], h1);
    gemm_bf16_k<2, 2, 64, 32, true,  false><<<gg, 256, SMB4>>>(
        h1, bf2,
        (const float*)d_in[4], (const float*)d_in[10], (const float*)d_in[16],
        h2, H1SZ, H2SZ);
    gemm_bf16_k<2, 1, 32, 96, false, true ><<<gg, 256, SMB4>>>(
        h2, bf3,
        (const float*)d_in[6], (const float*)d_in[12], (const float*)d_in[18],
        feat, H2SZ, 0);

    attn_k<<<dim3(NWIN*NWIN/2, BATCH), 128>>>(feat, pos, aout);
    convout_gemm_k<<<g1, 256, SMB>>>(aout, bfo, bo, x, out);
}